// round 1
// baseline (speedup 1.0000x reference)
#include <cuda_runtime.h>

#define A_SIZE   100000
#define V_SIZE   500000
#define D_DIM    128
#define L_TOK    64
#define TILE_A   64
#define NTHREADS 256
#define NBLOCKS  148

// ---------------- static device scratch (no allocations allowed) ----------------
__device__ __align__(16) float g_scores[A_SIZE];
__device__ __align__(16) float g_MT[L_TOK * D_DIM];   // M[l][j] = sum_k W1[j][128+k]*Qt[l][k]
__device__ __align__(16) float g_h1pre[D_DIM];        // b1[j] + hist . W1[j][0:128]
__device__ __align__(16) float g_stats[2];            // max, sumexp

// ---------------- K0: tiny precompute ----------------
__global__ void precompute_kernel(const float* __restrict__ W1,
                                  const float* __restrict__ b1,
                                  const float* __restrict__ Qt,
                                  const float* __restrict__ hist) {
    int j = threadIdx.x;  // 0..127
    if (blockIdx.x == L_TOK) {
        float acc = b1[j];
        #pragma unroll 4
        for (int k = 0; k < D_DIM; k++) acc += hist[k] * W1[j * 2 * D_DIM + k];
        g_h1pre[j] = acc;
    } else {
        int l = blockIdx.x;
        float acc = 0.f;
        #pragma unroll 4
        for (int k = 0; k < D_DIM; k++)
            acc += W1[j * 2 * D_DIM + D_DIM + k] * Qt[l * D_DIM + k];
        g_MT[l * D_DIM + j] = acc;
    }
}

// ---------------- main scoring kernel ----------------
// smem layout (floats):
//   qt  : 64*132
//   mt  : 64*132
//   w2  : 128*132
//   rel : 64*132
//   att : 64*68
//   h1  : 128
//   b2  : 128
//   part: 64*17
//   ids : 64 (int)
#define SM_QT   0
#define SM_MT   (SM_QT + 64 * 132)
#define SM_W2   (SM_MT + 64 * 132)
#define SM_REL  (SM_W2 + 128 * 132)
#define SM_ATT  (SM_REL + 64 * 132)
#define SM_H1   (SM_ATT + 64 * 68)
#define SM_B2   (SM_H1 + 128)
#define SM_PART (SM_B2 + 128)
#define SM_IDS  (SM_PART + 64 * 17)
#define SM_FLOATS (SM_IDS + 64)

__global__ __launch_bounds__(NTHREADS, 1)
void score_kernel(const int* __restrict__ ids_g,
                  const float* __restrict__ emb,
                  const float* __restrict__ Qt_g,
                  const float* __restrict__ W2_g,
                  const float* __restrict__ b2_g,
                  int nTiles) {
    extern __shared__ float sm[];
    float* s_qt   = sm + SM_QT;
    float* s_mt   = sm + SM_MT;
    float* s_w2   = sm + SM_W2;
    float* s_rel  = sm + SM_REL;
    float* s_att  = sm + SM_ATT;
    float* s_h1   = sm + SM_H1;
    float* s_b2   = sm + SM_B2;
    float* s_part = sm + SM_PART;
    int*   s_ids  = (int*)(sm + SM_IDS);

    const int tid = threadIdx.x;
    const int tx  = tid & 15;   // 16 cols: 8 j's / 4 tokens each
    const int ty  = tid >> 4;   // 16 rows: 4 actions each

    float4* qt4  = (float4*)s_qt;
    float4* mt4  = (float4*)s_mt;
    float4* w24  = (float4*)s_w2;
    float4* rel4 = (float4*)s_rel;

    // load loop-invariant operands once per CTA
    {
        const float4* Qg  = (const float4*)Qt_g;
        const float4* Mg  = (const float4*)g_MT;
        const float4* W2g = (const float4*)W2_g;
        for (int idx = tid; idx < 64 * 32; idx += NTHREADS) {
            int r = idx >> 5, c = idx & 31;
            qt4[r * 33 + c] = Qg[idx];
            mt4[r * 33 + c] = Mg[idx];
        }
        for (int idx = tid; idx < 128 * 32; idx += NTHREADS) {
            int r = idx >> 5, c = idx & 31;
            w24[r * 33 + c] = W2g[idx];
        }
        if (tid < 128) { s_h1[tid] = g_h1pre[tid]; s_b2[tid] = b2_g[tid]; }
    }
    __syncthreads();

    const float4* emb4 = (const float4*)emb;

    for (int tile = blockIdx.x; tile < nTiles; tile += gridDim.x) {
        const int base = tile * TILE_A;

        if (tid < TILE_A) {
            int a = base + tid;
            s_ids[tid] = (a < A_SIZE) ? ids_g[a] : 0;
        }
        __syncthreads();

        // ---- gather REL tile [64][128] ----
        for (int idx = tid; idx < 64 * 32; idx += NTHREADS) {
            int r = idx >> 5, c = idx & 31;
            rel4[r * 33 + c] = emb4[(size_t)s_ids[r] * 32 + c];
        }
        __syncthreads();

        // ---- stage B: ATT[a][t] = rel[a] . Qt[t]  (64x64x128) ----
        {
            float accB[4][4];
            #pragma unroll
            for (int i = 0; i < 4; i++)
                #pragma unroll
                for (int t = 0; t < 4; t++) accB[i][t] = 0.f;

            #pragma unroll 4
            for (int d4 = 0; d4 < 32; d4++) {
                float4 ra[4], qa[4];
                #pragma unroll
                for (int i = 0; i < 4; i++) ra[i] = rel4[(4 * ty + i) * 33 + d4];
                #pragma unroll
                for (int t = 0; t < 4; t++) qa[t] = qt4[(4 * tx + t) * 33 + d4];
                #pragma unroll
                for (int i = 0; i < 4; i++)
                    #pragma unroll
                    for (int t = 0; t < 4; t++)
                        accB[i][t] += ra[i].x * qa[t].x + ra[i].y * qa[t].y
                                    + ra[i].z * qa[t].z + ra[i].w * qa[t].w;
            }
            #pragma unroll
            for (int i = 0; i < 4; i++)
                #pragma unroll
                for (int t = 0; t < 4; t++)
                    s_att[(4 * ty + i) * 68 + 4 * tx + t] = accB[i][t];
        }
        __syncthreads();

        // ---- row softmax over 64 tokens (warp w handles actions 8w..8w+7) ----
        {
            const int w = tid >> 5, lane = tid & 31;
            for (int r = 0; r < 8; r++) {
                int a = w * 8 + r;
                float v1 = s_att[a * 68 + lane];
                float v2 = s_att[a * 68 + 32 + lane];
                float m = fmaxf(v1, v2);
                #pragma unroll
                for (int off = 16; off > 0; off >>= 1)
                    m = fmaxf(m, __shfl_xor_sync(0xFFFFFFFFu, m, off));
                float e1 = __expf(v1 - m);
                float e2 = __expf(v2 - m);
                float s = e1 + e2;
                #pragma unroll
                for (int off = 16; off > 0; off >>= 1)
                    s += __shfl_xor_sync(0xFFFFFFFFu, s, off);
                float inv = 1.f / s;
                s_att[a * 68 + lane]      = e1 * inv;
                s_att[a * 68 + 32 + lane] = e2 * inv;
            }
        }
        __syncthreads();

        // ---- stage C: hidden[a][j] = relu(h1pre[j] + sum_l w[a][l]*M[l][j]) ----
        float hid[4][8];
        {
            float accC[4][8];
            #pragma unroll
            for (int i = 0; i < 4; i++)
                #pragma unroll
                for (int j = 0; j < 8; j++) accC[i][j] = 0.f;

            #pragma unroll 2
            for (int l = 0; l < 64; l++) {
                float wv[4];
                #pragma unroll
                for (int i = 0; i < 4; i++) wv[i] = s_att[(4 * ty + i) * 68 + l];
                float4 m0 = mt4[l * 33 + 2 * tx];
                float4 m1 = mt4[l * 33 + 2 * tx + 1];
                #pragma unroll
                for (int i = 0; i < 4; i++) {
                    accC[i][0] += wv[i] * m0.x;  accC[i][1] += wv[i] * m0.y;
                    accC[i][2] += wv[i] * m0.z;  accC[i][3] += wv[i] * m0.w;
                    accC[i][4] += wv[i] * m1.x;  accC[i][5] += wv[i] * m1.y;
                    accC[i][6] += wv[i] * m1.z;  accC[i][7] += wv[i] * m1.w;
                }
            }
            #pragma unroll
            for (int i = 0; i < 4; i++)
                #pragma unroll
                for (int j = 0; j < 8; j++)
                    hid[i][j] = fmaxf(accC[i][j] + s_h1[8 * tx + j], 0.f);
        }

        // ---- stage D: v[a][j] = sum_d rel[a][d]*W2[d][j]; score = hid.v + rel.b2 ----
        float pb[4] = {0.f, 0.f, 0.f, 0.f};
        #pragma unroll
        for (int dd = 0; dd < 8; dd++) {
            float b2v = s_b2[8 * tx + dd];
            #pragma unroll
            for (int i = 0; i < 4; i++)
                pb[i] += s_rel[(4 * ty + i) * 132 + 8 * tx + dd] * b2v;
        }
        {
            float vv[4][8];
            #pragma unroll
            for (int i = 0; i < 4; i++)
                #pragma unroll
                for (int j = 0; j < 8; j++) vv[i][j] = 0.f;

            #pragma unroll 2
            for (int d = 0; d < 128; d++) {
                float ra[4];
                #pragma unroll
                for (int i = 0; i < 4; i++) ra[i] = s_rel[(4 * ty + i) * 132 + d];
                float4 w0 = w24[d * 33 + 2 * tx];
                float4 w1 = w24[d * 33 + 2 * tx + 1];
                #pragma unroll
                for (int i = 0; i < 4; i++) {
                    vv[i][0] += ra[i] * w0.x;  vv[i][1] += ra[i] * w0.y;
                    vv[i][2] += ra[i] * w0.z;  vv[i][3] += ra[i] * w0.w;
                    vv[i][4] += ra[i] * w1.x;  vv[i][5] += ra[i] * w1.y;
                    vv[i][6] += ra[i] * w1.z;  vv[i][7] += ra[i] * w1.w;
                }
            }
            float p[4];
            #pragma unroll
            for (int i = 0; i < 4; i++) {
                float s = pb[i];
                #pragma unroll
                for (int j = 0; j < 8; j++) s += hid[i][j] * vv[i][j];
                p[i] = s;
            }
            #pragma unroll
            for (int i = 0; i < 4; i++)
                s_part[(4 * ty + i) * 17 + tx] = p[i];
        }
        __syncthreads();

        if (tid < TILE_A) {
            float s = 0.f;
            #pragma unroll
            for (int x = 0; x < 16; x++) s += s_part[tid * 17 + x];
            int a = base + tid;
            if (a < A_SIZE) g_scores[a] = s;
        }
        // next-iter gather writes rel only after the post-ids __syncthreads,
        // and score readers use s_part only — no extra barrier needed here.
    }
}

// ---------------- global softmax over A ----------------
__global__ void reduce_kernel() {
    __shared__ float red[32];
    __shared__ float s_bmax;
    const int tid = threadIdx.x;
    const int lane = tid & 31, wid = tid >> 5;

    float m = -1e30f;
    for (int i = tid; i < A_SIZE; i += 1024) m = fmaxf(m, g_scores[i]);
    #pragma unroll
    for (int off = 16; off > 0; off >>= 1)
        m = fmaxf(m, __shfl_xor_sync(0xFFFFFFFFu, m, off));
    if (lane == 0) red[wid] = m;
    __syncthreads();
    if (wid == 0) {
        float mm = red[lane];
        #pragma unroll
        for (int off = 16; off > 0; off >>= 1)
            mm = fmaxf(mm, __shfl_xor_sync(0xFFFFFFFFu, mm, off));
        if (lane == 0) s_bmax = mm;
    }
    __syncthreads();
    const float mx = s_bmax;

    float s = 0.f;
    for (int i = tid; i < A_SIZE; i += 1024) s += __expf(g_scores[i] - mx);
    #pragma unroll
    for (int off = 16; off > 0; off >>= 1)
        s += __shfl_xor_sync(0xFFFFFFFFu, s, off);
    if (lane == 0) red[wid] = s;
    __syncthreads();
    if (wid == 0) {
        float ss = red[lane];
        #pragma unroll
        for (int off = 16; off > 0; off >>= 1)
            ss += __shfl_xor_sync(0xFFFFFFFFu, ss, off);
        if (lane == 0) { g_stats[0] = mx; g_stats[1] = ss; }
    }
}

__global__ void norm_kernel(float* __restrict__ out) {
    int i = blockIdx.x * blockDim.x + threadIdx.x;
    if (i < A_SIZE) {
        float inv = 1.f / g_stats[1];
        out[i] = __expf(g_scores[i] - g_stats[0]) * inv;
    }
}

// ---------------- launch ----------------
extern "C" void kernel_launch(void* const* d_in, const int* in_sizes, int n_in,
                              void* d_out, int out_size) {
    const int*   action_ids = (const int*)d_in[0];
    const float* emb        = (const float*)d_in[1];
    const float* question_t = (const float*)d_in[2];
    const float* history_t  = (const float*)d_in[3];
    const float* W1         = (const float*)d_in[4];
    const float* b1         = (const float*)d_in[5];
    const float* W2         = (const float*)d_in[6];
    const float* b2         = (const float*)d_in[7];
    float* out = (float*)d_out;

    precompute_kernel<<<L_TOK + 1, 128>>>(W1, b1, question_t, history_t);

    const int smem_bytes = SM_FLOATS * (int)sizeof(float);
    cudaFuncSetAttribute(score_kernel,
                         cudaFuncAttributeMaxDynamicSharedMemorySize, smem_bytes);
    const int nTiles = (A_SIZE + TILE_A - 1) / TILE_A;
    score_kernel<<<NBLOCKS, NTHREADS, smem_bytes>>>(action_ids, emb, question_t,
                                                    W2, b2, nTiles);

    reduce_kernel<<<1, 1024>>>();
    norm_kernel<<<(A_SIZE + 1023) / 1024, 1024>>>(out);
}

// round 4
// speedup vs baseline: 1.9791x; 1.9791x over previous
#include <cuda_runtime.h>
#include <cuda_bf16.h>
#include <cstdint>

#define A_SIZE   100000
#define D_DIM    128
#define L_TOK    64
#define TILE_A   128
#define NBLOCKS  148
#define NTILES   ((A_SIZE + TILE_A - 1) / TILE_A)
#define NTHREADS 256

// ---------------- smem layout (bytes) ----------------
#define SM_RELH  0                     // [128 rows][256B] bf16, xor-swizzled
#define SM_RELL  (SM_RELH + 32768)
#define SM_QTH   (SM_RELL + 32768)     // u32 [64][66]  (QtT pairs, k-major)
#define SM_QTL   (SM_QTH + 16896)
#define SM_MH    (SM_QTL + 16896)      // u32 [32][130] (M pairs, k=l)
#define SM_ML    (SM_MH + 16640)
#define SM_W2H   (SM_ML + 16640)       // u32 [64][130] (W2 pairs, k=d, natural layout)
#define SM_W2L   (SM_W2H + 33280)
#define SM_H1    (SM_W2L + 33280)      // f32 [128]
#define SM_B2    (SM_H1 + 512)         // f32 [128]
#define SM_DB2   (SM_B2 + 512)         // f32 [256]
#define SM_TOTAL (SM_DB2 + 1024)

// ---------------- device scratch ----------------
__device__ __align__(16) float g_scores[A_SIZE];
__device__ __align__(16) float g_h1pre[D_DIM];
__device__ __align__(16) float g_stats[2];
__device__ __align__(16) float g_pmax[128];
__device__ __align__(16) float g_psum[128];
__device__ __align__(16) __nv_bfloat16 g_qt_hi[L_TOK * D_DIM];   // [t][d]
__device__ __align__(16) __nv_bfloat16 g_qt_lo[L_TOK * D_DIM];
__device__ __align__(16) __nv_bfloat16 g_m_hi[L_TOK * D_DIM];    // [l][j]
__device__ __align__(16) __nv_bfloat16 g_m_lo[L_TOK * D_DIM];
__device__ __align__(16) __nv_bfloat16 g_w2_hi[D_DIM * D_DIM];   // [d][j] = W2[d][j]  (natural!)
__device__ __align__(16) __nv_bfloat16 g_w2_lo[D_DIM * D_DIM];

// ---------------- helpers ----------------
__device__ __forceinline__ uint16_t bf16_bits(float x) {
    __nv_bfloat16 h = __float2bfloat16(x);
    return *reinterpret_cast<uint16_t*>(&h);
}
__device__ __forceinline__ float bf16_val(uint16_t b) {
    __nv_bfloat16 h = *reinterpret_cast<__nv_bfloat16*>(&b);
    return __bfloat162float(h);
}
// pack two floats (x -> low half, y -> high half) into bf16x2 hi & lo(residual)
__device__ __forceinline__ void split_pack(float x, float y, uint32_t& hp, uint32_t& lp) {
    uint16_t hx = bf16_bits(x), hy = bf16_bits(y);
    uint16_t lx = bf16_bits(x - bf16_val(hx)), ly = bf16_bits(y - bf16_val(hy));
    hp = ((uint32_t)hy << 16) | hx;
    lp = ((uint32_t)ly << 16) | lx;
}

__device__ __forceinline__ uint32_t smem_u32(const void* p) {
    uint32_t a;
    asm("{ .reg .u64 t; cvta.to.shared.u64 t, %1; cvt.u32.u64 %0, t; }" : "=r"(a) : "l"(p));
    return a;
}

__device__ __forceinline__ void ldmA(uint32_t (&r)[4], uint32_t addr) {
    asm volatile("ldmatrix.sync.aligned.m8n8.x4.shared.b16 {%0,%1,%2,%3}, [%4];"
                 : "=r"(r[0]), "=r"(r[1]), "=r"(r[2]), "=r"(r[3]) : "r"(addr));
}

__device__ __forceinline__ void mma16816(float (&c)[4], const uint32_t (&a)[4],
                                         uint32_t b0, uint32_t b1) {
    asm volatile(
        "mma.sync.aligned.m16n8k16.row.col.f32.bf16.bf16.f32 "
        "{%0,%1,%2,%3}, {%4,%5,%6,%7}, {%8,%9}, {%0,%1,%2,%3};"
        : "+f"(c[0]), "+f"(c[1]), "+f"(c[2]), "+f"(c[3])
        : "r"(a[0]), "r"(a[1]), "r"(a[2]), "r"(a[3]), "r"(b0), "r"(b1));
}

// ---------------- prep kernels ----------------
__global__ void prep_h1(const float* __restrict__ W1, const float* __restrict__ b1,
                        const float* __restrict__ hist) {
    int j = threadIdx.x;
    float acc = b1[j];
    #pragma unroll 4
    for (int k = 0; k < D_DIM; k++) acc += hist[k] * W1[j * 2 * D_DIM + k];
    g_h1pre[j] = acc;
}

__global__ void prep_qt(const float* __restrict__ Qt) {
    int i = blockIdx.x * 128 + threadIdx.x;  // t*128 + d
    float x = Qt[i];
    uint16_t h = bf16_bits(x);
    g_qt_hi[i] = *reinterpret_cast<__nv_bfloat16*>(&h);
    uint16_t l = bf16_bits(x - bf16_val(h));
    g_qt_lo[i] = *reinterpret_cast<__nv_bfloat16*>(&l);
}

__global__ void prep_mt(const float* __restrict__ W1, const float* __restrict__ Qt) {
    int j = blockIdx.x, l = threadIdx.x;   // 128 blocks x 64 threads
    float acc = 0.f;
    #pragma unroll 4
    for (int k = 0; k < D_DIM; k++)
        acc += W1[j * 2 * D_DIM + D_DIM + k] * Qt[l * D_DIM + k];
    uint16_t h = bf16_bits(acc);
    g_m_hi[l * D_DIM + j] = *reinterpret_cast<__nv_bfloat16*>(&h);
    uint16_t lo = bf16_bits(acc - bf16_val(h));
    g_m_lo[l * D_DIM + j] = *reinterpret_cast<__nv_bfloat16*>(&lo);
}

// FIXED: keep W2 in natural [d][j] layout (v[a][j] = sum_d rel[a][d] * W2[d][j])
__global__ void prep_w2(const float* __restrict__ W2) {
    int d = blockIdx.x, j = threadIdx.x;   // 128 x 128
    float x = W2[d * D_DIM + j];
    uint16_t h = bf16_bits(x);
    g_w2_hi[d * D_DIM + j] = *reinterpret_cast<__nv_bfloat16*>(&h);
    uint16_t l = bf16_bits(x - bf16_val(h));
    g_w2_lo[d * D_DIM + j] = *reinterpret_cast<__nv_bfloat16*>(&l);
}

// ---------------- main score kernel ----------------
__global__ __launch_bounds__(NTHREADS, 1)
void score_kernel(const int* __restrict__ ids_g,
                  const float* __restrict__ emb,
                  const float* __restrict__ b2_g) {
    extern __shared__ char smem[];
    const int tid  = threadIdx.x;
    const int wid  = tid >> 5;
    const int lane = tid & 31;
    const int q    = lane & 3;      // quad index
    const int nidx = lane >> 2;     // n within 8-col tile

    float*    s_h1  = (float*)(smem + SM_H1);
    float*    s_b2  = (float*)(smem + SM_B2);
    float*    s_db2 = (float*)(smem + SM_DB2);
    uint32_t* s_qth = (uint32_t*)(smem + SM_QTH);
    uint32_t* s_qtl = (uint32_t*)(smem + SM_QTL);
    uint32_t* s_mh  = (uint32_t*)(smem + SM_MH);
    uint32_t* s_ml  = (uint32_t*)(smem + SM_ML);
    uint32_t* s_w2h = (uint32_t*)(smem + SM_W2H);
    uint32_t* s_w2l = (uint32_t*)(smem + SM_W2L);

    const uint32_t sb32 = smem_u32(smem);

    // ---- one-time fills ----
    if (tid < 128) { s_h1[tid] = g_h1pre[tid]; s_b2[tid] = b2_g[tid]; }
    for (int i = tid; i < 64 * 64; i += NTHREADS) {       // QtT pairs: row d2, col t
        int t = i >> 6, d2 = i & 63;
        const __nv_bfloat16* ph = g_qt_hi + t * D_DIM + 2 * d2;
        const __nv_bfloat16* pl = g_qt_lo + t * D_DIM + 2 * d2;
        s_qth[d2 * 66 + t] = ((uint32_t)*(const uint16_t*)(ph + 1) << 16) | *(const uint16_t*)ph;
        s_qtl[d2 * 66 + t] = ((uint32_t)*(const uint16_t*)(pl + 1) << 16) | *(const uint16_t*)pl;
    }
    for (int i = tid; i < 32 * 128; i += NTHREADS) {      // M pairs: row l2, col j
        int l2 = i >> 7, j = i & 127;
        s_mh[l2 * 130 + j] =
            ((uint32_t)*(const uint16_t*)(g_m_hi + (2 * l2 + 1) * D_DIM + j) << 16) |
             *(const uint16_t*)(g_m_hi + (2 * l2) * D_DIM + j);
        s_ml[l2 * 130 + j] =
            ((uint32_t)*(const uint16_t*)(g_m_lo + (2 * l2 + 1) * D_DIM + j) << 16) |
             *(const uint16_t*)(g_m_lo + (2 * l2) * D_DIM + j);
    }
    for (int i = tid; i < 64 * 128; i += NTHREADS) {      // W2 pairs: row d2, col j
        int d2 = i >> 7, j = i & 127;
        s_w2h[d2 * 130 + j] =
            ((uint32_t)*(const uint16_t*)(g_w2_hi + (2 * d2 + 1) * D_DIM + j) << 16) |
             *(const uint16_t*)(g_w2_hi + (2 * d2) * D_DIM + j);
        s_w2l[d2 * 130 + j] =
            ((uint32_t)*(const uint16_t*)(g_w2_lo + (2 * d2 + 1) * D_DIM + j) << 16) |
             *(const uint16_t*)(g_w2_lo + (2 * d2) * D_DIM + j);
    }
    __syncthreads();

    const float4* emb4 = (const float4*)emb;

    for (int tile = blockIdx.x; tile < NTILES; tile += gridDim.x) {
        // ================= gather rel -> swizzled smem (hi/lo) =================
        {
            const int row = tid >> 1;
            const int a   = tile * TILE_A + row;
            const int id  = (a < A_SIZE) ? ids_g[a] : 0;
            const float4* r4 = emb4 + (size_t)id * 32;
            float db2 = 0.f;
            #pragma unroll
            for (int i = 0; i < 8; i++) {
                const int c = 2 * i + (tid & 1);          // 16B chunk, 8 d's
                float4 v0 = r4[c * 2], v1 = r4[c * 2 + 1];
                const float* bb = s_b2 + c * 8;
                db2 += v0.x * bb[0] + v0.y * bb[1] + v0.z * bb[2] + v0.w * bb[3]
                     + v1.x * bb[4] + v1.y * bb[5] + v1.z * bb[6] + v1.w * bb[7];
                uint4 hi, lo;
                split_pack(v0.x, v0.y, hi.x, lo.x);
                split_pack(v0.z, v0.w, hi.y, lo.y);
                split_pack(v1.x, v1.y, hi.z, lo.z);
                split_pack(v1.z, v1.w, hi.w, lo.w);
                const int b = (c * 16) ^ ((row & 7) << 4);
                *(uint4*)(smem + SM_RELH + row * 256 + b) = hi;
                *(uint4*)(smem + SM_RELL + row * 256 + b) = lo;
            }
            s_db2[tid] = db2;
        }
        __syncthreads();

        // ================= rel A-fragments (reused by stages B and D) =================
        uint32_t Ah[8][4], Al[8][4];
        {
            const int rowa = 16 * wid + (lane & 15);
            const int kh   = ((lane >> 4) & 1) << 4;
            #pragma unroll
            for (int kt = 0; kt < 8; kt++) {
                const int b = (kt * 32 + kh) ^ ((rowa & 7) << 4);
                ldmA(Ah[kt], sb32 + SM_RELH + rowa * 256 + b);
                ldmA(Al[kt], sb32 + SM_RELL + rowa * 256 + b);
            }
        }

        // ================= stage B: att = rel . QtT  (3-way split) =================
        float catt[8][4];
        #pragma unroll
        for (int nt = 0; nt < 8; nt++)
            #pragma unroll
            for (int x = 0; x < 4; x++) catt[nt][x] = 0.f;

        #pragma unroll
        for (int nt = 0; nt < 8; nt++) {
            #pragma unroll
            for (int kt = 0; kt < 8; kt++) {
                const int rb = kt * 8 + q;
                const int cb = nt * 8 + nidx;
                uint32_t b0h = s_qth[rb * 66 + cb];
                uint32_t b1h = s_qth[(rb + 4) * 66 + cb];
                uint32_t b0l = s_qtl[rb * 66 + cb];
                uint32_t b1l = s_qtl[(rb + 4) * 66 + cb];
                mma16816(catt[nt], Ah[kt], b0h, b1h);
                mma16816(catt[nt], Al[kt], b0h, b1h);
                mma16816(catt[nt], Ah[kt], b0l, b1l);
            }
        }

        // ================= softmax in fragments (row = action) =================
        uint32_t Wh[4][4], Wl[4][4];
        {
            float m0 = -1e30f, m1 = -1e30f;
            #pragma unroll
            for (int nt = 0; nt < 8; nt++) {
                m0 = fmaxf(m0, fmaxf(catt[nt][0], catt[nt][1]));
                m1 = fmaxf(m1, fmaxf(catt[nt][2], catt[nt][3]));
            }
            m0 = fmaxf(m0, __shfl_xor_sync(0xFFFFFFFFu, m0, 1));
            m0 = fmaxf(m0, __shfl_xor_sync(0xFFFFFFFFu, m0, 2));
            m1 = fmaxf(m1, __shfl_xor_sync(0xFFFFFFFFu, m1, 1));
            m1 = fmaxf(m1, __shfl_xor_sync(0xFFFFFFFFu, m1, 2));
            float s0 = 0.f, s1 = 0.f;
            #pragma unroll
            for (int nt = 0; nt < 8; nt++) {
                catt[nt][0] = __expf(catt[nt][0] - m0);
                catt[nt][1] = __expf(catt[nt][1] - m0);
                catt[nt][2] = __expf(catt[nt][2] - m1);
                catt[nt][3] = __expf(catt[nt][3] - m1);
                s0 += catt[nt][0] + catt[nt][1];
                s1 += catt[nt][2] + catt[nt][3];
            }
            s0 += __shfl_xor_sync(0xFFFFFFFFu, s0, 1);
            s0 += __shfl_xor_sync(0xFFFFFFFFu, s0, 2);
            s1 += __shfl_xor_sync(0xFFFFFFFFu, s1, 1);
            s1 += __shfl_xor_sync(0xFFFFFFFFu, s1, 2);
            const float i0 = 1.f / s0, i1 = 1.f / s1;
            // accumulator layout == A-operand layout: pack directly
            #pragma unroll
            for (int j = 0; j < 4; j++) {
                split_pack(catt[2 * j][0] * i0, catt[2 * j][1] * i0, Wh[j][0], Wl[j][0]);
                split_pack(catt[2 * j][2] * i1, catt[2 * j][3] * i1, Wh[j][1], Wl[j][1]);
                split_pack(catt[2 * j + 1][0] * i0, catt[2 * j + 1][1] * i0, Wh[j][2], Wl[j][2]);
                split_pack(catt[2 * j + 1][2] * i1, catt[2 * j + 1][3] * i1, Wh[j][3], Wl[j][3]);
            }
        }

        // ================= fused stages C & D + epilogue =================
        float sc0 = 0.f, sc1 = 0.f;
        #pragma unroll
        for (int nt = 0; nt < 16; nt++) {
            float cc[4] = {0.f, 0.f, 0.f, 0.f};
            float cv[4] = {0.f, 0.f, 0.f, 0.f};
            const int cb = nt * 8 + nidx;
            // C: hiddenpre = w . M   (K = 64)
            #pragma unroll
            for (int kt = 0; kt < 4; kt++) {
                const int rb = kt * 8 + q;
                uint32_t b0h = s_mh[rb * 130 + cb];
                uint32_t b1h = s_mh[(rb + 4) * 130 + cb];
                uint32_t b0l = s_ml[rb * 130 + cb];
                uint32_t b1l = s_ml[(rb + 4) * 130 + cb];
                mma16816(cc, Wh[kt], b0h, b1h);
                mma16816(cc, Wl[kt], b0h, b1h);
                mma16816(cc, Wh[kt], b0l, b1l);
            }
            // D: v = rel . W2   (K = 128)
            #pragma unroll
            for (int kt = 0; kt < 8; kt++) {
                const int rb = kt * 8 + q;
                uint32_t b0h = s_w2h[rb * 130 + cb];
                uint32_t b1h = s_w2h[(rb + 4) * 130 + cb];
                uint32_t b0l = s_w2l[rb * 130 + cb];
                uint32_t b1l = s_w2l[(rb + 4) * 130 + cb];
                mma16816(cv, Ah[kt], b0h, b1h);
                mma16816(cv, Al[kt], b0h, b1h);
                mma16816(cv, Ah[kt], b0l, b1l);
            }
            const int j0 = nt * 8 + 2 * q;
            const float h1a = s_h1[j0], h1b = s_h1[j0 + 1];
            sc0 += fmaxf(cc[0] + h1a, 0.f) * cv[0] + fmaxf(cc[1] + h1b, 0.f) * cv[1];
            sc1 += fmaxf(cc[2] + h1a, 0.f) * cv[2] + fmaxf(cc[3] + h1b, 0.f) * cv[3];
        }

        // quad-reduce and write scores
        sc0 += __shfl_xor_sync(0xFFFFFFFFu, sc0, 1);
        sc0 += __shfl_xor_sync(0xFFFFFFFFu, sc0, 2);
        sc1 += __shfl_xor_sync(0xFFFFFFFFu, sc1, 1);
        sc1 += __shfl_xor_sync(0xFFFFFFFFu, sc1, 2);
        if (q == 0) {
            const int r0 = 16 * wid + nidx;
            const int r1 = r0 + 8;
            const int a0 = tile * TILE_A + r0;
            const int a1 = tile * TILE_A + r1;
            if (a0 < A_SIZE) g_scores[a0] = sc0 + s_db2[2 * r0] + s_db2[2 * r0 + 1];
            if (a1 < A_SIZE) g_scores[a1] = sc1 + s_db2[2 * r1] + s_db2[2 * r1 + 1];
        }
        __syncthreads();
    }
}

// ---------------- global softmax over A ----------------
#define NB_RED 98

__global__ void reduce1_kernel() {
    __shared__ float red[32];
    __shared__ float s_m;
    const int tid = threadIdx.x, lane = tid & 31, w = tid >> 5;
    float m = -1e30f;
    for (int i = blockIdx.x * 1024 + tid; i < A_SIZE; i += NB_RED * 1024)
        m = fmaxf(m, g_scores[i]);
    #pragma unroll
    for (int o = 16; o > 0; o >>= 1) m = fmaxf(m, __shfl_xor_sync(0xFFFFFFFFu, m, o));
    if (lane == 0) red[w] = m;
    __syncthreads();
    if (w == 0) {
        float mm = red[lane];
        #pragma unroll
        for (int o = 16; o > 0; o >>= 1) mm = fmaxf(mm, __shfl_xor_sync(0xFFFFFFFFu, mm, o));
        if (lane == 0) s_m = mm;
    }
    __syncthreads();
    const float bm = s_m;
    float s = 0.f;
    for (int i = blockIdx.x * 1024 + tid; i < A_SIZE; i += NB_RED * 1024)
        s += __expf(g_scores[i] - bm);
    #pragma unroll
    for (int o = 16; o > 0; o >>= 1) s += __shfl_xor_sync(0xFFFFFFFFu, s, o);
    if (lane == 0) red[w] = s;
    __syncthreads();
    if (w == 0) {
        float ss = red[lane];
        #pragma unroll
        for (int o = 16; o > 0; o >>= 1) ss += __shfl_xor_sync(0xFFFFFFFFu, ss, o);
        if (lane == 0) { g_pmax[blockIdx.x] = bm; g_psum[blockIdx.x] = ss; }
    }
}

__global__ void reduce2_kernel() {
    const int tid = threadIdx.x;  // 128 threads
    float m = (tid < NB_RED) ? g_pmax[tid] : -1e30f;
    #pragma unroll
    for (int o = 16; o > 0; o >>= 1) m = fmaxf(m, __shfl_xor_sync(0xFFFFFFFFu, m, o));
    __shared__ float red[4];
    __shared__ float s_m;
    if ((tid & 31) == 0) red[tid >> 5] = m;
    __syncthreads();
    if (tid == 0) s_m = fmaxf(fmaxf(red[0], red[1]), fmaxf(red[2], red[3]));
    __syncthreads();
    const float gm = s_m;
    float z = (tid < NB_RED) ? g_psum[tid] * __expf(g_pmax[tid] - gm) : 0.f;
    #pragma unroll
    for (int o = 16; o > 0; o >>= 1) z += __shfl_xor_sync(0xFFFFFFFFu, z, o);
    __shared__ float redz[4];
    if ((tid & 31) == 0) redz[tid >> 5] = z;
    __syncthreads();
    if (tid == 0) {
        g_stats[0] = gm;
        g_stats[1] = redz[0] + redz[1] + redz[2] + redz[3];
    }
}

__global__ void norm_kernel(float* __restrict__ out) {
    int i = blockIdx.x * blockDim.x + threadIdx.x;
    if (i < A_SIZE) {
        float inv = 1.f / g_stats[1];
        out[i] = __expf(g_scores[i] - g_stats[0]) * inv;
    }
}

// ---------------- launch ----------------
extern "C" void kernel_launch(void* const* d_in, const int* in_sizes, int n_in,
                              void* d_out, int out_size) {
    const int*   action_ids = (const int*)d_in[0];
    const float* emb        = (const float*)d_in[1];
    const float* question_t = (const float*)d_in[2];
    const float* history_t  = (const float*)d_in[3];
    const float* W1         = (const float*)d_in[4];
    const float* b1         = (const float*)d_in[5];
    const float* W2         = (const float*)d_in[6];
    const float* b2         = (const float*)d_in[7];
    float* out = (float*)d_out;

    prep_h1<<<1, 128>>>(W1, b1, history_t);
    prep_qt<<<L_TOK, 128>>>(question_t);
    prep_mt<<<D_DIM, L_TOK>>>(W1, question_t);
    prep_w2<<<D_DIM, D_DIM>>>(W2);

    cudaFuncSetAttribute(score_kernel,
                         cudaFuncAttributeMaxDynamicSharedMemorySize, SM_TOTAL);
    score_kernel<<<NBLOCKS, NTHREADS, SM_TOTAL>>>(action_ids, emb, b2);

    reduce1_kernel<<<NB_RED, 1024>>>();
    reduce2_kernel<<<1, 128>>>();
    norm_kernel<<<(A_SIZE + 255) / 256, 256>>>(out);
}

// round 5
// speedup vs baseline: 3.5498x; 1.7937x over previous
#include <cuda_runtime.h>
#include <cuda_bf16.h>
#include <cstdint>

#define A_SIZE   100000
#define D_DIM    128
#define L_TOK    64
#define TILE_A   128
#define NBLOCKS  148
#define NTILES   ((A_SIZE + TILE_A - 1) / TILE_A)
#define NTHREADS 256

// ---------------- smem layout (bytes) ----------------
#define SM_RELH  0                     // [128 rows][256B] bf16, xor-swizzled (A operand)
#define SM_RELL  (SM_RELH + 32768)
#define SM_QTH   (SM_RELL + 32768)     // [64 t-rows][256B]  Qt[t][d]   (B, n-major)
#define SM_QTL   (SM_QTH + 16384)
#define SM_MH    (SM_QTL + 16384)      // [128 j-rows][128B] M[l][j] stored [j][l]
#define SM_ML    (SM_MH + 16384)
#define SM_W2H   (SM_ML + 16384)       // [128 j-rows][256B] W2[d][j] stored [j][d]
#define SM_W2L   (SM_W2H + 32768)
#define SM_H1    (SM_W2L + 32768)      // f32 [128]
#define SM_B2    (SM_H1 + 512)         // f32 [128]
#define SM_DB2   (SM_B2 + 512)         // f32 [256]
#define SM_TOTAL (SM_DB2 + 1024)

// ---------------- device scratch ----------------
__device__ __align__(16) float g_scores[A_SIZE];
__device__ __align__(16) float g_h1pre[D_DIM];
__device__ __align__(16) float g_stats[2];
__device__ __align__(16) float g_pmax[128];
__device__ __align__(16) float g_psum[128];
__device__ __align__(16) uint16_t g_qt_hi[L_TOK * D_DIM];   // [t][d]
__device__ __align__(16) uint16_t g_qt_lo[L_TOK * D_DIM];
__device__ __align__(16) uint16_t g_m_hi[D_DIM * L_TOK];    // [j][l]
__device__ __align__(16) uint16_t g_m_lo[D_DIM * L_TOK];
__device__ __align__(16) uint16_t g_w2_hi[D_DIM * D_DIM];   // [j][d] = W2[d][j]
__device__ __align__(16) uint16_t g_w2_lo[D_DIM * D_DIM];

// ---------------- helpers ----------------
__device__ __forceinline__ uint16_t bf16_bits(float x) {
    __nv_bfloat16 h = __float2bfloat16(x);
    return *reinterpret_cast<uint16_t*>(&h);
}
__device__ __forceinline__ float bf16_val(uint16_t b) {
    __nv_bfloat16 h = *reinterpret_cast<__nv_bfloat16*>(&b);
    return __bfloat162float(h);
}
__device__ __forceinline__ void split_pack(float x, float y, uint32_t& hp, uint32_t& lp) {
    uint16_t hx = bf16_bits(x), hy = bf16_bits(y);
    uint16_t lx = bf16_bits(x - bf16_val(hx)), ly = bf16_bits(y - bf16_val(hy));
    hp = ((uint32_t)hy << 16) | hx;
    lp = ((uint32_t)ly << 16) | lx;
}
__device__ __forceinline__ uint32_t smem_u32(const void* p) {
    uint32_t a;
    asm("{ .reg .u64 t; cvta.to.shared.u64 t, %1; cvt.u32.u64 %0, t; }" : "=r"(a) : "l"(p));
    return a;
}
__device__ __forceinline__ void ldm4(uint32_t (&r)[4], uint32_t addr) {
    asm volatile("ldmatrix.sync.aligned.m8n8.x4.shared.b16 {%0,%1,%2,%3}, [%4];"
                 : "=r"(r[0]), "=r"(r[1]), "=r"(r[2]), "=r"(r[3]) : "r"(addr));
}
__device__ __forceinline__ void mma16816(float (&c)[4], const uint32_t (&a)[4],
                                         uint32_t b0, uint32_t b1) {
    asm volatile(
        "mma.sync.aligned.m16n8k16.row.col.f32.bf16.bf16.f32 "
        "{%0,%1,%2,%3}, {%4,%5,%6,%7}, {%8,%9}, {%0,%1,%2,%3};"
        : "+f"(c[0]), "+f"(c[1]), "+f"(c[2]), "+f"(c[3])
        : "r"(a[0]), "r"(a[1]), "r"(a[2]), "r"(a[3]), "r"(b0), "r"(b1));
}

// ---------------- fused prep kernel ----------------
__global__ void prep_all(const float* __restrict__ W1, const float* __restrict__ b1,
                         const float* __restrict__ Qt, const float* __restrict__ hist,
                         const float* __restrict__ W2) {
    const int b = blockIdx.x, tid = threadIdx.x;
    if (b < 64) {                        // Qt row t=b, col d=tid
        int i = b * 128 + tid;
        float x = Qt[i];
        uint16_t h = bf16_bits(x);
        g_qt_hi[i] = h;
        g_qt_lo[i] = bf16_bits(x - bf16_val(h));
    } else if (b < 192) {                // j = b-64
        int j = b - 64;
        float x = W2[tid * D_DIM + j];   // store W2[d][j] at [j][d]
        uint16_t h = bf16_bits(x);
        g_w2_hi[j * D_DIM + tid] = h;
        g_w2_lo[j * D_DIM + tid] = bf16_bits(x - bf16_val(h));
        if (tid < 64) {
            int l = tid;
            float acc = 0.f;
            #pragma unroll 4
            for (int k = 0; k < D_DIM; k++)
                acc += W1[j * 2 * D_DIM + D_DIM + k] * Qt[l * D_DIM + k];
            uint16_t mh = bf16_bits(acc);
            g_m_hi[j * L_TOK + l] = mh;
            g_m_lo[j * L_TOK + l] = bf16_bits(acc - bf16_val(mh));
        }
    } else {                             // h1pre
        int j = tid;
        float acc = b1[j];
        #pragma unroll 4
        for (int k = 0; k < D_DIM; k++) acc += hist[k] * W1[j * 2 * D_DIM + k];
        g_h1pre[j] = acc;
    }
}

// ---------------- main score kernel ----------------
__global__ __launch_bounds__(NTHREADS, 1)
void score_kernel(const int* __restrict__ ids_g,
                  const float* __restrict__ emb,
                  const float* __restrict__ b2_g) {
    extern __shared__ char smem[];
    const int tid  = threadIdx.x;
    const int wid  = tid >> 5;
    const int lane = tid & 31;
    const int q    = lane & 3;
    const int nidx = lane >> 2;

    float* s_h1  = (float*)(smem + SM_H1);
    float* s_b2  = (float*)(smem + SM_B2);
    float* s_db2 = (float*)(smem + SM_DB2);
    const uint32_t sb32 = smem_u32(smem);

    // ---- one-time fills (swizzled 16B chunks; row-major n x k) ----
    if (tid < 128) { s_h1[tid] = g_h1pre[tid]; s_b2[tid] = b2_g[tid]; }
    {
        const uint4* qh = (const uint4*)g_qt_hi;   // 8 bf16 per uint4
        const uint4* ql = (const uint4*)g_qt_lo;
        for (int i = tid; i < 64 * 16; i += NTHREADS) {   // Qt: 64 rows x 16 chunks
            int r = i >> 4, c = i & 15;
            int o = r * 256 + ((c * 16) ^ ((r & 7) << 4));
            *(uint4*)(smem + SM_QTH + o) = qh[i];
            *(uint4*)(smem + SM_QTL + o) = ql[i];
        }
        const uint4* mh = (const uint4*)g_m_hi;
        const uint4* ml = (const uint4*)g_m_lo;
        for (int i = tid; i < 128 * 8; i += NTHREADS) {   // M: 128 rows x 8 chunks
            int r = i >> 3, c = i & 7;
            int o = r * 128 + ((c * 16) ^ ((r & 7) << 4));
            *(uint4*)(smem + SM_MH + o) = mh[i];
            *(uint4*)(smem + SM_ML + o) = ml[i];
        }
        const uint4* wh = (const uint4*)g_w2_hi;
        const uint4* wl = (const uint4*)g_w2_lo;
        for (int i = tid; i < 128 * 16; i += NTHREADS) {  // W2: 128 rows x 16 chunks
            int r = i >> 4, c = i & 15;
            int o = r * 256 + ((c * 16) ^ ((r & 7) << 4));
            *(uint4*)(smem + SM_W2H + o) = wh[i];
            *(uint4*)(smem + SM_W2L + o) = wl[i];
        }
    }
    __syncthreads();

    // per-lane ldmatrix-B address pieces
    const int lrow = lane & 7;
    const int lgrp = lane >> 3;
    const int nadd = (lgrp & 2) << 2;    // 0 or 8 (n-row offset)
    const int cpar = lgrp & 1;           // chunk parity (k 0-7 vs 8-15)
    const int lr4  = lrow << 4;
    const uint32_t qtB  = sb32 + SM_QTH + (uint32_t)((nadd + lrow) * 256);
    const uint32_t qtBl = sb32 + SM_QTL + (uint32_t)((nadd + lrow) * 256);
    const uint32_t mB   = sb32 + SM_MH  + (uint32_t)((nadd + lrow) * 128);
    const uint32_t mBl  = sb32 + SM_ML  + (uint32_t)((nadd + lrow) * 128);
    const uint32_t w2B  = sb32 + SM_W2H + (uint32_t)((nadd + lrow) * 256);
    const uint32_t w2Bl = sb32 + SM_W2L + (uint32_t)((nadd + lrow) * 256);

    const float4* emb4 = (const float4*)emb;

    for (int tile = blockIdx.x; tile < NTILES; tile += gridDim.x) {
        // ================= gather rel -> swizzled smem (hi/lo) =================
        {
            const int row = tid >> 1;
            const int a   = tile * TILE_A + row;
            const int id  = (a < A_SIZE) ? ids_g[a] : 0;
            const float4* r4 = emb4 + (size_t)id * 32;
            float db2 = 0.f;
            #pragma unroll
            for (int i = 0; i < 8; i++) {
                const int c = 2 * i + (tid & 1);
                float4 v0 = r4[c * 2], v1 = r4[c * 2 + 1];
                const float* bb = s_b2 + c * 8;
                db2 += v0.x * bb[0] + v0.y * bb[1] + v0.z * bb[2] + v0.w * bb[3]
                     + v1.x * bb[4] + v1.y * bb[5] + v1.z * bb[6] + v1.w * bb[7];
                uint4 hi, lo;
                split_pack(v0.x, v0.y, hi.x, lo.x);
                split_pack(v0.z, v0.w, hi.y, lo.y);
                split_pack(v1.x, v1.y, hi.z, lo.z);
                split_pack(v1.z, v1.w, hi.w, lo.w);
                const int b = (c * 16) ^ ((row & 7) << 4);
                *(uint4*)(smem + SM_RELH + row * 256 + b) = hi;
                *(uint4*)(smem + SM_RELL + row * 256 + b) = lo;
            }
            s_db2[tid] = db2;
        }
        __syncthreads();

        // ================= rel A-fragments (stages B and D) =================
        uint32_t Ah[8][4], Al[8][4];
        {
            const int rowa = 16 * wid + (lane & 15);
            const int kh   = ((lane >> 4) & 1) << 4;
            #pragma unroll
            for (int kt = 0; kt < 8; kt++) {
                const int b = (kt * 32 + kh) ^ ((rowa & 7) << 4);
                ldm4(Ah[kt], sb32 + SM_RELH + rowa * 256 + b);
                ldm4(Al[kt], sb32 + SM_RELL + rowa * 256 + b);
            }
        }

        // ================= stage B: att = rel . QtT =================
        float catt[8][4];
        #pragma unroll
        for (int nt = 0; nt < 8; nt++)
            #pragma unroll
            for (int x = 0; x < 4; x++) catt[nt][x] = 0.f;

        #pragma unroll
        for (int kt = 0; kt < 8; kt++) {
            const uint32_t swz = (uint32_t)((((kt * 2 + cpar) * 16)) ^ lr4);
            #pragma unroll
            for (int np = 0; np < 4; np++) {
                uint32_t bh[4], bl[4];
                ldm4(bh, qtB  + np * 4096 + swz);
                ldm4(bl, qtBl + np * 4096 + swz);
                mma16816(catt[2 * np],     Ah[kt], bh[0], bh[1]);
                mma16816(catt[2 * np],     Al[kt], bh[0], bh[1]);
                mma16816(catt[2 * np],     Ah[kt], bl[0], bl[1]);
                mma16816(catt[2 * np + 1], Ah[kt], bh[2], bh[3]);
                mma16816(catt[2 * np + 1], Al[kt], bh[2], bh[3]);
                mma16816(catt[2 * np + 1], Ah[kt], bl[2], bl[3]);
            }
        }

        // ================= softmax in fragments (row = action) =================
        uint32_t Wh[4][4], Wl[4][4];
        {
            float m0 = -1e30f, m1 = -1e30f;
            #pragma unroll
            for (int nt = 0; nt < 8; nt++) {
                m0 = fmaxf(m0, fmaxf(catt[nt][0], catt[nt][1]));
                m1 = fmaxf(m1, fmaxf(catt[nt][2], catt[nt][3]));
            }
            m0 = fmaxf(m0, __shfl_xor_sync(0xFFFFFFFFu, m0, 1));
            m0 = fmaxf(m0, __shfl_xor_sync(0xFFFFFFFFu, m0, 2));
            m1 = fmaxf(m1, __shfl_xor_sync(0xFFFFFFFFu, m1, 1));
            m1 = fmaxf(m1, __shfl_xor_sync(0xFFFFFFFFu, m1, 2));
            float s0 = 0.f, s1 = 0.f;
            #pragma unroll
            for (int nt = 0; nt < 8; nt++) {
                catt[nt][0] = __expf(catt[nt][0] - m0);
                catt[nt][1] = __expf(catt[nt][1] - m0);
                catt[nt][2] = __expf(catt[nt][2] - m1);
                catt[nt][3] = __expf(catt[nt][3] - m1);
                s0 += catt[nt][0] + catt[nt][1];
                s1 += catt[nt][2] + catt[nt][3];
            }
            s0 += __shfl_xor_sync(0xFFFFFFFFu, s0, 1);
            s0 += __shfl_xor_sync(0xFFFFFFFFu, s0, 2);
            s1 += __shfl_xor_sync(0xFFFFFFFFu, s1, 1);
            s1 += __shfl_xor_sync(0xFFFFFFFFu, s1, 2);
            const float i0 = 1.f / s0, i1 = 1.f / s1;
            #pragma unroll
            for (int j = 0; j < 4; j++) {
                split_pack(catt[2 * j][0] * i0, catt[2 * j][1] * i0, Wh[j][0], Wl[j][0]);
                split_pack(catt[2 * j][2] * i1, catt[2 * j][3] * i1, Wh[j][1], Wl[j][1]);
                split_pack(catt[2 * j + 1][0] * i0, catt[2 * j + 1][1] * i0, Wh[j][2], Wl[j][2]);
                split_pack(catt[2 * j + 1][2] * i1, catt[2 * j + 1][3] * i1, Wh[j][3], Wl[j][3]);
            }
        }

        // ================= fused stages C & D + epilogue =================
        float sc0 = 0.f, sc1 = 0.f;
        #pragma unroll
        for (int np = 0; np < 8; np++) {
            float cc0[4] = {0.f, 0.f, 0.f, 0.f};
            float cc1[4] = {0.f, 0.f, 0.f, 0.f};
            float cv0[4] = {0.f, 0.f, 0.f, 0.f};
            float cv1[4] = {0.f, 0.f, 0.f, 0.f};
            // C: hiddenpre = w . M   (K = 64)
            #pragma unroll
            for (int kt = 0; kt < 4; kt++) {
                const uint32_t swz = (uint32_t)((((kt * 2 + cpar) * 16)) ^ lr4);
                uint32_t bh[4], bl[4];
                ldm4(bh, mB  + np * 2048 + swz);
                ldm4(bl, mBl + np * 2048 + swz);
                mma16816(cc0, Wh[kt], bh[0], bh[1]);
                mma16816(cc0, Wl[kt], bh[0], bh[1]);
                mma16816(cc0, Wh[kt], bl[0], bl[1]);
                mma16816(cc1, Wh[kt], bh[2], bh[3]);
                mma16816(cc1, Wl[kt], bh[2], bh[3]);
                mma16816(cc1, Wh[kt], bl[2], bl[3]);
            }
            // D: v = rel . W2   (K = 128)
            #pragma unroll
            for (int kt = 0; kt < 8; kt++) {
                const uint32_t swz = (uint32_t)((((kt * 2 + cpar) * 16)) ^ lr4);
                uint32_t bh[4], bl[4];
                ldm4(bh, w2B  + np * 4096 + swz);
                ldm4(bl, w2Bl + np * 4096 + swz);
                mma16816(cv0, Ah[kt], bh[0], bh[1]);
                mma16816(cv0, Al[kt], bh[0], bh[1]);
                mma16816(cv0, Ah[kt], bl[0], bl[1]);
                mma16816(cv1, Ah[kt], bh[2], bh[3]);
                mma16816(cv1, Al[kt], bh[2], bh[3]);
                mma16816(cv1, Ah[kt], bl[2], bl[3]);
            }
            {
                const int j0 = (2 * np) * 8 + 2 * q;
                const float h1a = s_h1[j0], h1b = s_h1[j0 + 1];
                sc0 += fmaxf(cc0[0] + h1a, 0.f) * cv0[0] + fmaxf(cc0[1] + h1b, 0.f) * cv0[1];
                sc1 += fmaxf(cc0[2] + h1a, 0.f) * cv0[2] + fmaxf(cc0[3] + h1b, 0.f) * cv0[3];
            }
            {
                const int j0 = (2 * np + 1) * 8 + 2 * q;
                const float h1a = s_h1[j0], h1b = s_h1[j0 + 1];
                sc0 += fmaxf(cc1[0] + h1a, 0.f) * cv1[0] + fmaxf(cc1[1] + h1b, 0.f) * cv1[1];
                sc1 += fmaxf(cc1[2] + h1a, 0.f) * cv1[2] + fmaxf(cc1[3] + h1b, 0.f) * cv1[3];
            }
        }

        // quad-reduce and write scores
        sc0 += __shfl_xor_sync(0xFFFFFFFFu, sc0, 1);
        sc0 += __shfl_xor_sync(0xFFFFFFFFu, sc0, 2);
        sc1 += __shfl_xor_sync(0xFFFFFFFFu, sc1, 1);
        sc1 += __shfl_xor_sync(0xFFFFFFFFu, sc1, 2);
        if (q == 0) {
            const int r0 = 16 * wid + nidx;
            const int r1 = r0 + 8;
            const int a0 = tile * TILE_A + r0;
            const int a1 = tile * TILE_A + r1;
            if (a0 < A_SIZE) g_scores[a0] = sc0 + s_db2[2 * r0] + s_db2[2 * r0 + 1];
            if (a1 < A_SIZE) g_scores[a1] = sc1 + s_db2[2 * r1] + s_db2[2 * r1 + 1];
        }
        __syncthreads();
    }
}

// ---------------- global softmax over A ----------------
#define NB_RED 98

__global__ void reduce1_kernel() {
    __shared__ float red[32];
    __shared__ float s_m;
    const int tid = threadIdx.x, lane = tid & 31, w = tid >> 5;
    float m = -1e30f;
    for (int i = blockIdx.x * 1024 + tid; i < A_SIZE; i += NB_RED * 1024)
        m = fmaxf(m, g_scores[i]);
    #pragma unroll
    for (int o = 16; o > 0; o >>= 1) m = fmaxf(m, __shfl_xor_sync(0xFFFFFFFFu, m, o));
    if (lane == 0) red[w] = m;
    __syncthreads();
    if (w == 0) {
        float mm = red[lane];
        #pragma unroll
        for (int o = 16; o > 0; o >>= 1) mm = fmaxf(mm, __shfl_xor_sync(0xFFFFFFFFu, mm, o));
        if (lane == 0) s_m = mm;
    }
    __syncthreads();
    const float bm = s_m;
    float s = 0.f;
    for (int i = blockIdx.x * 1024 + tid; i < A_SIZE; i += NB_RED * 1024)
        s += __expf(g_scores[i] - bm);
    #pragma unroll
    for (int o = 16; o > 0; o >>= 1) s += __shfl_xor_sync(0xFFFFFFFFu, s, o);
    if (lane == 0) red[w] = s;
    __syncthreads();
    if (w == 0) {
        float ss = red[lane];
        #pragma unroll
        for (int o = 16; o > 0; o >>= 1) ss += __shfl_xor_sync(0xFFFFFFFFu, ss, o);
        if (lane == 0) { g_pmax[blockIdx.x] = bm; g_psum[blockIdx.x] = ss; }
    }
}

__global__ void reduce2_kernel() {
    const int tid = threadIdx.x;  // 128 threads
    float m = (tid < NB_RED) ? g_pmax[tid] : -1e30f;
    #pragma unroll
    for (int o = 16; o > 0; o >>= 1) m = fmaxf(m, __shfl_xor_sync(0xFFFFFFFFu, m, o));
    __shared__ float red[4];
    __shared__ float s_m;
    if ((tid & 31) == 0) red[tid >> 5] = m;
    __syncthreads();
    if (tid == 0) s_m = fmaxf(fmaxf(red[0], red[1]), fmaxf(red[2], red[3]));
    __syncthreads();
    const float gm = s_m;
    float z = (tid < NB_RED) ? g_psum[tid] * __expf(g_pmax[tid] - gm) : 0.f;
    #pragma unroll
    for (int o = 16; o > 0; o >>= 1) z += __shfl_xor_sync(0xFFFFFFFFu, z, o);
    __shared__ float redz[4];
    if ((tid & 31) == 0) redz[tid >> 5] = z;
    __syncthreads();
    if (tid == 0) {
        g_stats[0] = gm;
        g_stats[1] = redz[0] + redz[1] + redz[2] + redz[3];
    }
}

__global__ void norm_kernel(float* __restrict__ out) {
    int i = blockIdx.x * blockDim.x + threadIdx.x;
    if (i < A_SIZE) {
        float inv = 1.f / g_stats[1];
        out[i] = __expf(g_scores[i] - g_stats[0]) * inv;
    }
}

// ---------------- launch ----------------
extern "C" void kernel_launch(void* const* d_in, const int* in_sizes, int n_in,
                              void* d_out, int out_size) {
    const int*   action_ids = (const int*)d_in[0];
    const float* emb        = (const float*)d_in[1];
    const float* question_t = (const float*)d_in[2];
    const float* history_t  = (const float*)d_in[3];
    const float* W1         = (const float*)d_in[4];
    const float* b1         = (const float*)d_in[5];
    const float* W2         = (const float*)d_in[6];
    const float* b2         = (const float*)d_in[7];
    float* out = (float*)d_out;

    prep_all<<<193, 128>>>(W1, b1, question_t, history_t, W2);

    cudaFuncSetAttribute(score_kernel,
                         cudaFuncAttributeMaxDynamicSharedMemorySize, SM_TOTAL);
    score_kernel<<<NBLOCKS, NTHREADS, SM_TOTAL>>>(action_ids, emb, b2);

    reduce1_kernel<<<NB_RED, 1024>>>();
    reduce2_kernel<<<1, 128>>>();
    norm_kernel<<<(A_SIZE + 255) / 256, 256>>>(out);
}

// round 6
// speedup vs baseline: 3.6504x; 1.0283x over previous
#include <cuda_runtime.h>
#include <cuda_bf16.h>
#include <cstdint>

#define A_SIZE   100000
#define D_DIM    128
#define L_TOK    64
#define TILE_A   128
#define NBLOCKS  148
#define NTILES   ((A_SIZE + TILE_A - 1) / TILE_A)
#define NTHREADS 256

// ---------------- smem layout (bytes) ----------------
#define SM_RELH  0                     // [128 rows][256B] bf16, xor-swizzled (A operand)
#define SM_RELL  (SM_RELH + 32768)
#define SM_QTH   (SM_RELL + 32768)     // [64 t-rows][256B]  Qt[t][d]   (B, n-major)
#define SM_QTL   (SM_QTH + 16384)
#define SM_MH    (SM_QTL + 16384)      // [128 j-rows][128B] M[l][j] stored [j][l]
#define SM_ML    (SM_MH + 16384)
#define SM_W2H   (SM_ML + 16384)       // [128 j-rows][256B] W2[d][j] stored [j][d]
#define SM_W2L   (SM_W2H + 32768)
#define SM_H1    (SM_W2L + 32768)      // f32 [128]
#define SM_B2    (SM_H1 + 512)         // f32 [128]
#define SM_DB2   (SM_B2 + 512)         // f32 [256]
#define SM_RM    (SM_DB2 + 1024)       // f32 [8]
#define SM_RZ    (SM_RM + 32)          // f32 [8]
#define SM_FLAG  (SM_RZ + 32)          // int
#define SM_TOTAL (SM_FLAG + 16)

// ---------------- device scratch ----------------
__device__ __align__(16) float g_scores[A_SIZE];
__device__ __align__(16) float g_h1pre[D_DIM];
__device__ __align__(16) float g_stats[2];
__device__ __align__(16) float g_pmax[256];
__device__ __align__(16) float g_psum[256];
__device__ int g_done;
__device__ __align__(16) uint16_t g_qt_hi[L_TOK * D_DIM];   // [t][d]
__device__ __align__(16) uint16_t g_qt_lo[L_TOK * D_DIM];
__device__ __align__(16) uint16_t g_m_hi[D_DIM * L_TOK];    // [j][l]
__device__ __align__(16) uint16_t g_m_lo[D_DIM * L_TOK];
__device__ __align__(16) uint16_t g_w2_hi[D_DIM * D_DIM];   // [j][d] = W2[d][j]
__device__ __align__(16) uint16_t g_w2_lo[D_DIM * D_DIM];

// ---------------- helpers ----------------
__device__ __forceinline__ uint16_t bf16_bits(float x) {
    __nv_bfloat16 h = __float2bfloat16(x);
    return *reinterpret_cast<uint16_t*>(&h);
}
__device__ __forceinline__ float bf16_val(uint16_t b) {
    __nv_bfloat16 h = *reinterpret_cast<__nv_bfloat16*>(&b);
    return __bfloat162float(h);
}
__device__ __forceinline__ void split_pack(float x, float y, uint32_t& hp, uint32_t& lp) {
    uint16_t hx = bf16_bits(x), hy = bf16_bits(y);
    uint16_t lx = bf16_bits(x - bf16_val(hx)), ly = bf16_bits(y - bf16_val(hy));
    hp = ((uint32_t)hy << 16) | hx;
    lp = ((uint32_t)ly << 16) | lx;
}
__device__ __forceinline__ uint32_t smem_u32(const void* p) {
    uint32_t a;
    asm("{ .reg .u64 t; cvta.to.shared.u64 t, %1; cvt.u32.u64 %0, t; }" : "=r"(a) : "l"(p));
    return a;
}
__device__ __forceinline__ void ldm4(uint32_t (&r)[4], uint32_t addr) {
    asm volatile("ldmatrix.sync.aligned.m8n8.x4.shared.b16 {%0,%1,%2,%3}, [%4];"
                 : "=r"(r[0]), "=r"(r[1]), "=r"(r[2]), "=r"(r[3]) : "r"(addr));
}
__device__ __forceinline__ void mma16816(float (&c)[4], const uint32_t (&a)[4],
                                         uint32_t b0, uint32_t b1) {
    asm volatile(
        "mma.sync.aligned.m16n8k16.row.col.f32.bf16.bf16.f32 "
        "{%0,%1,%2,%3}, {%4,%5,%6,%7}, {%8,%9}, {%0,%1,%2,%3};"
        : "+f"(c[0]), "+f"(c[1]), "+f"(c[2]), "+f"(c[3])
        : "r"(a[0]), "r"(a[1]), "r"(a[2]), "r"(a[3]), "r"(b0), "r"(b1));
}
// online softmax merge: (m,z) <- merge((m,z),(om,oz))
__device__ __forceinline__ void oz_merge(float& m, float& z, float om, float oz) {
    float nm = fmaxf(m, om);
    z = z * __expf(m - nm) + oz * __expf(om - nm);
    m = nm;
}

// ---------------- fused prep kernel ----------------
__global__ void prep_all(const float* __restrict__ W1, const float* __restrict__ b1,
                         const float* __restrict__ Qt, const float* __restrict__ hist,
                         const float* __restrict__ W2) {
    const int b = blockIdx.x, tid = threadIdx.x;
    if (b < 64) {                        // Qt row t=b, col d=tid
        int i = b * 128 + tid;
        float x = Qt[i];
        uint16_t h = bf16_bits(x);
        g_qt_hi[i] = h;
        g_qt_lo[i] = bf16_bits(x - bf16_val(h));
    } else if (b < 192) {                // j = b-64
        int j = b - 64;
        float x = W2[tid * D_DIM + j];   // store W2[d][j] at [j][d]
        uint16_t h = bf16_bits(x);
        g_w2_hi[j * D_DIM + tid] = h;
        g_w2_lo[j * D_DIM + tid] = bf16_bits(x - bf16_val(h));
        if (tid < 64) {
            int l = tid;
            float acc = 0.f;
            #pragma unroll 4
            for (int k = 0; k < D_DIM; k++)
                acc += W1[j * 2 * D_DIM + D_DIM + k] * Qt[l * D_DIM + k];
            uint16_t mh = bf16_bits(acc);
            g_m_hi[j * L_TOK + l] = mh;
            g_m_lo[j * L_TOK + l] = bf16_bits(acc - bf16_val(mh));
        }
    } else {                             // h1pre + counter reset
        int j = tid;
        float acc = b1[j];
        #pragma unroll 4
        for (int k = 0; k < D_DIM; k++) acc += hist[k] * W1[j * 2 * D_DIM + k];
        g_h1pre[j] = acc;
        if (tid == 0) g_done = 0;
    }
}

// ---------------- main score kernel ----------------
__global__ __launch_bounds__(NTHREADS, 1)
void score_kernel(const int* __restrict__ ids_g,
                  const float* __restrict__ emb,
                  const float* __restrict__ b2_g) {
    extern __shared__ char smem[];
    const int tid  = threadIdx.x;
    const int wid  = tid >> 5;
    const int lane = tid & 31;
    const int q    = lane & 3;
    const int nidx = lane >> 2;

    float* s_h1  = (float*)(smem + SM_H1);
    float* s_b2  = (float*)(smem + SM_B2);
    float* s_db2 = (float*)(smem + SM_DB2);
    float* s_rm  = (float*)(smem + SM_RM);
    float* s_rz  = (float*)(smem + SM_RZ);
    int*   s_fl  = (int*)(smem + SM_FLAG);
    const uint32_t sb32 = smem_u32(smem);

    // ---- one-time fills (swizzled 16B chunks; row-major n x k) ----
    if (tid < 128) { s_h1[tid] = g_h1pre[tid]; s_b2[tid] = b2_g[tid]; }
    {
        const uint4* qh = (const uint4*)g_qt_hi;
        const uint4* ql = (const uint4*)g_qt_lo;
        for (int i = tid; i < 64 * 16; i += NTHREADS) {
            int r = i >> 4, c = i & 15;
            int o = r * 256 + ((c * 16) ^ ((r & 7) << 4));
            *(uint4*)(smem + SM_QTH + o) = qh[i];
            *(uint4*)(smem + SM_QTL + o) = ql[i];
        }
        const uint4* mh = (const uint4*)g_m_hi;
        const uint4* ml = (const uint4*)g_m_lo;
        for (int i = tid; i < 128 * 8; i += NTHREADS) {
            int r = i >> 3, c = i & 7;
            int o = r * 128 + ((c * 16) ^ ((r & 7) << 4));
            *(uint4*)(smem + SM_MH + o) = mh[i];
            *(uint4*)(smem + SM_ML + o) = ml[i];
        }
        const uint4* wh = (const uint4*)g_w2_hi;
        const uint4* wl = (const uint4*)g_w2_lo;
        for (int i = tid; i < 128 * 16; i += NTHREADS) {
            int r = i >> 4, c = i & 15;
            int o = r * 256 + ((c * 16) ^ ((r & 7) << 4));
            *(uint4*)(smem + SM_W2H + o) = wh[i];
            *(uint4*)(smem + SM_W2L + o) = wl[i];
        }
    }
    __syncthreads();

    // per-lane ldmatrix-B address pieces
    const int lrow = lane & 7;
    const int lgrp = lane >> 3;
    const int nadd = (lgrp & 2) << 2;
    const int cpar = lgrp & 1;
    const int lr4  = lrow << 4;
    const uint32_t qtB  = sb32 + SM_QTH + (uint32_t)((nadd + lrow) * 256);
    const uint32_t qtBl = sb32 + SM_QTL + (uint32_t)((nadd + lrow) * 256);
    const uint32_t mB   = sb32 + SM_MH  + (uint32_t)((nadd + lrow) * 128);
    const uint32_t mBl  = sb32 + SM_ML  + (uint32_t)((nadd + lrow) * 128);
    const uint32_t w2B  = sb32 + SM_W2H + (uint32_t)((nadd + lrow) * 256);
    const uint32_t w2Bl = sb32 + SM_W2L + (uint32_t)((nadd + lrow) * 256);

    const float4* emb4 = (const float4*)emb;

    // online softmax accumulators (finite sentinel to avoid inf-inf)
    float lm = -1e30f, lz = 0.f;

    for (int tile = blockIdx.x; tile < NTILES; tile += gridDim.x) {
        // ================= gather rel -> swizzled smem (hi/lo) =================
        {
            const int row = tid >> 1;
            const int a   = tile * TILE_A + row;
            const int id  = (a < A_SIZE) ? ids_g[a] : 0;
            const float4* r4 = emb4 + (size_t)id * 32;
            // batch all 16 loads first (MLP=16, single latency wait)
            float4 v[16];
            #pragma unroll
            for (int i = 0; i < 8; i++) {
                const int c = 2 * i + (tid & 1);
                v[2 * i]     = r4[c * 2];
                v[2 * i + 1] = r4[c * 2 + 1];
            }
            float db2 = 0.f;
            #pragma unroll
            for (int i = 0; i < 8; i++) {
                const int c = 2 * i + (tid & 1);
                float4 v0 = v[2 * i], v1 = v[2 * i + 1];
                const float* bb = s_b2 + c * 8;
                db2 += v0.x * bb[0] + v0.y * bb[1] + v0.z * bb[2] + v0.w * bb[3]
                     + v1.x * bb[4] + v1.y * bb[5] + v1.z * bb[6] + v1.w * bb[7];
                uint4 hi, lo;
                split_pack(v0.x, v0.y, hi.x, lo.x);
                split_pack(v0.z, v0.w, hi.y, lo.y);
                split_pack(v1.x, v1.y, hi.z, lo.z);
                split_pack(v1.z, v1.w, hi.w, lo.w);
                const int b = (c * 16) ^ ((row & 7) << 4);
                *(uint4*)(smem + SM_RELH + row * 256 + b) = hi;
                *(uint4*)(smem + SM_RELL + row * 256 + b) = lo;
            }
            s_db2[tid] = db2;
        }
        __syncthreads();

        // ================= rel A-fragments (stages B and D) =================
        uint32_t Ah[8][4], Al[8][4];
        {
            const int rowa = 16 * wid + (lane & 15);
            const int kh   = ((lane >> 4) & 1) << 4;
            #pragma unroll
            for (int kt = 0; kt < 8; kt++) {
                const int b = (kt * 32 + kh) ^ ((rowa & 7) << 4);
                ldm4(Ah[kt], sb32 + SM_RELH + rowa * 256 + b);
                ldm4(Al[kt], sb32 + SM_RELL + rowa * 256 + b);
            }
        }

        // ================= stage B: att = rel . QtT =================
        float catt[8][4];
        #pragma unroll
        for (int nt = 0; nt < 8; nt++)
            #pragma unroll
            for (int x = 0; x < 4; x++) catt[nt][x] = 0.f;

        #pragma unroll
        for (int kt = 0; kt < 8; kt++) {
            const uint32_t swz = (uint32_t)((((kt * 2 + cpar) * 16)) ^ lr4);
            #pragma unroll
            for (int np = 0; np < 4; np++) {
                uint32_t bh[4], bl[4];
                ldm4(bh, qtB  + np * 4096 + swz);
                ldm4(bl, qtBl + np * 4096 + swz);
                mma16816(catt[2 * np],     Ah[kt], bh[0], bh[1]);
                mma16816(catt[2 * np],     Al[kt], bh[0], bh[1]);
                mma16816(catt[2 * np],     Ah[kt], bl[0], bl[1]);
                mma16816(catt[2 * np + 1], Ah[kt], bh[2], bh[3]);
                mma16816(catt[2 * np + 1], Al[kt], bh[2], bh[3]);
                mma16816(catt[2 * np + 1], Ah[kt], bl[2], bl[3]);
            }
        }

        // ================= softmax in fragments (row = action) =================
        uint32_t Wh[4][4], Wl[4][4];
        {
            float m0 = -1e30f, m1 = -1e30f;
            #pragma unroll
            for (int nt = 0; nt < 8; nt++) {
                m0 = fmaxf(m0, fmaxf(catt[nt][0], catt[nt][1]));
                m1 = fmaxf(m1, fmaxf(catt[nt][2], catt[nt][3]));
            }
            m0 = fmaxf(m0, __shfl_xor_sync(0xFFFFFFFFu, m0, 1));
            m0 = fmaxf(m0, __shfl_xor_sync(0xFFFFFFFFu, m0, 2));
            m1 = fmaxf(m1, __shfl_xor_sync(0xFFFFFFFFu, m1, 1));
            m1 = fmaxf(m1, __shfl_xor_sync(0xFFFFFFFFu, m1, 2));
            float s0 = 0.f, s1 = 0.f;
            #pragma unroll
            for (int nt = 0; nt < 8; nt++) {
                catt[nt][0] = __expf(catt[nt][0] - m0);
                catt[nt][1] = __expf(catt[nt][1] - m0);
                catt[nt][2] = __expf(catt[nt][2] - m1);
                catt[nt][3] = __expf(catt[nt][3] - m1);
                s0 += catt[nt][0] + catt[nt][1];
                s1 += catt[nt][2] + catt[nt][3];
            }
            s0 += __shfl_xor_sync(0xFFFFFFFFu, s0, 1);
            s0 += __shfl_xor_sync(0xFFFFFFFFu, s0, 2);
            s1 += __shfl_xor_sync(0xFFFFFFFFu, s1, 1);
            s1 += __shfl_xor_sync(0xFFFFFFFFu, s1, 2);
            const float i0 = 1.f / s0, i1 = 1.f / s1;
            #pragma unroll
            for (int j = 0; j < 4; j++) {
                split_pack(catt[2 * j][0] * i0, catt[2 * j][1] * i0, Wh[j][0], Wl[j][0]);
                split_pack(catt[2 * j][2] * i1, catt[2 * j][3] * i1, Wh[j][1], Wl[j][1]);
                split_pack(catt[2 * j + 1][0] * i0, catt[2 * j + 1][1] * i0, Wh[j][2], Wl[j][2]);
                split_pack(catt[2 * j + 1][2] * i1, catt[2 * j + 1][3] * i1, Wh[j][3], Wl[j][3]);
            }
        }

        // ================= fused stages C & D + epilogue =================
        float sc0 = 0.f, sc1 = 0.f;
        #pragma unroll
        for (int np = 0; np < 8; np++) {
            float cc0[4] = {0.f, 0.f, 0.f, 0.f};
            float cc1[4] = {0.f, 0.f, 0.f, 0.f};
            float cv0[4] = {0.f, 0.f, 0.f, 0.f};
            float cv1[4] = {0.f, 0.f, 0.f, 0.f};
            #pragma unroll
            for (int kt = 0; kt < 4; kt++) {
                const uint32_t swz = (uint32_t)((((kt * 2 + cpar) * 16)) ^ lr4);
                uint32_t bh[4], bl[4];
                ldm4(bh, mB  + np * 2048 + swz);
                ldm4(bl, mBl + np * 2048 + swz);
                mma16816(cc0, Wh[kt], bh[0], bh[1]);
                mma16816(cc0, Wl[kt], bh[0], bh[1]);
                mma16816(cc0, Wh[kt], bl[0], bl[1]);
                mma16816(cc1, Wh[kt], bh[2], bh[3]);
                mma16816(cc1, Wl[kt], bh[2], bh[3]);
                mma16816(cc1, Wh[kt], bl[2], bl[3]);
            }
            #pragma unroll
            for (int kt = 0; kt < 8; kt++) {
                const uint32_t swz = (uint32_t)((((kt * 2 + cpar) * 16)) ^ lr4);
                uint32_t bh[4], bl[4];
                ldm4(bh, w2B  + np * 4096 + swz);
                ldm4(bl, w2Bl + np * 4096 + swz);
                mma16816(cv0, Ah[kt], bh[0], bh[1]);
                mma16816(cv0, Al[kt], bh[0], bh[1]);
                mma16816(cv0, Ah[kt], bl[0], bl[1]);
                mma16816(cv1, Ah[kt], bh[2], bh[3]);
                mma16816(cv1, Al[kt], bh[2], bh[3]);
                mma16816(cv1, Ah[kt], bl[2], bl[3]);
            }
            {
                const int j0 = (2 * np) * 8 + 2 * q;
                const float h1a = s_h1[j0], h1b = s_h1[j0 + 1];
                sc0 += fmaxf(cc0[0] + h1a, 0.f) * cv0[0] + fmaxf(cc0[1] + h1b, 0.f) * cv0[1];
                sc1 += fmaxf(cc0[2] + h1a, 0.f) * cv0[2] + fmaxf(cc0[3] + h1b, 0.f) * cv0[3];
            }
            {
                const int j0 = (2 * np + 1) * 8 + 2 * q;
                const float h1a = s_h1[j0], h1b = s_h1[j0 + 1];
                sc0 += fmaxf(cc1[0] + h1a, 0.f) * cv1[0] + fmaxf(cc1[1] + h1b, 0.f) * cv1[1];
                sc1 += fmaxf(cc1[2] + h1a, 0.f) * cv1[2] + fmaxf(cc1[3] + h1b, 0.f) * cv1[3];
            }
        }

        // quad-reduce, write scores, update online (m,z)
        sc0 += __shfl_xor_sync(0xFFFFFFFFu, sc0, 1);
        sc0 += __shfl_xor_sync(0xFFFFFFFFu, sc0, 2);
        sc1 += __shfl_xor_sync(0xFFFFFFFFu, sc1, 1);
        sc1 += __shfl_xor_sync(0xFFFFFFFFu, sc1, 2);
        if (q == 0) {
            const int r0 = 16 * wid + nidx;
            const int r1 = r0 + 8;
            const int a0 = tile * TILE_A + r0;
            const int a1 = tile * TILE_A + r1;
            if (a0 < A_SIZE) {
                float s = sc0 + s_db2[2 * r0] + s_db2[2 * r0 + 1];
                g_scores[a0] = s;
                float nm = fmaxf(lm, s);
                lz = lz * __expf(lm - nm) + __expf(s - nm);
                lm = nm;
            }
            if (a1 < A_SIZE) {
                float s = sc1 + s_db2[2 * r1] + s_db2[2 * r1 + 1];
                g_scores[a1] = s;
                float nm = fmaxf(lm, s);
                lz = lz * __expf(lm - nm) + __expf(s - nm);
                lm = nm;
            }
        }
        __syncthreads();
    }

    // ================= fused block-level softmax reduction =================
    #pragma unroll
    for (int o = 16; o > 0; o >>= 1) {
        float om = __shfl_xor_sync(0xFFFFFFFFu, lm, o);
        float oz = __shfl_xor_sync(0xFFFFFFFFu, lz, o);
        oz_merge(lm, lz, om, oz);
    }
    if (lane == 0) { s_rm[wid] = lm; s_rz[wid] = lz; }
    __syncthreads();
    if (tid == 0) {
        float M = s_rm[0], Z = s_rz[0];
        #pragma unroll
        for (int w = 1; w < 8; w++) oz_merge(M, Z, s_rm[w], s_rz[w]);
        g_pmax[blockIdx.x] = M;
        g_psum[blockIdx.x] = Z;
        __threadfence();
        int old = atomicAdd(&g_done, 1);
        s_fl[0] = (old == (int)gridDim.x - 1) ? 1 : 0;
    }
    __syncthreads();
    if (s_fl[0] && wid == 0) {
        // last block: merge all per-block partials
        float M = -1e30f, Z = 0.f;
        for (int i = lane; i < (int)gridDim.x; i += 32)
            oz_merge(M, Z, g_pmax[i], g_psum[i]);
        #pragma unroll
        for (int o = 16; o > 0; o >>= 1) {
            float om = __shfl_xor_sync(0xFFFFFFFFu, M, o);
            float oz = __shfl_xor_sync(0xFFFFFFFFu, Z, o);
            oz_merge(M, Z, om, oz);
        }
        if (lane == 0) { g_stats[0] = M; g_stats[1] = Z; }
    }
}

// ---------------- normalize ----------------
__global__ void norm_kernel(float* __restrict__ out) {
    int i = blockIdx.x * blockDim.x + threadIdx.x;
    if (i < A_SIZE) {
        float inv = 1.f / g_stats[1];
        out[i] = __expf(g_scores[i] - g_stats[0]) * inv;
    }
}

// ---------------- launch ----------------
extern "C" void kernel_launch(void* const* d_in, const int* in_sizes, int n_in,
                              void* d_out, int out_size) {
    const int*   action_ids = (const int*)d_in[0];
    const float* emb        = (const float*)d_in[1];
    const float* question_t = (const float*)d_in[2];
    const float* history_t  = (const float*)d_in[3];
    const float* W1         = (const float*)d_in[4];
    const float* b1         = (const float*)d_in[5];
    const float* W2         = (const float*)d_in[6];
    const float* b2         = (const float*)d_in[7];
    float* out = (float*)d_out;

    prep_all<<<193, 128>>>(W1, b1, question_t, history_t, W2);

    cudaFuncSetAttribute(score_kernel,
                         cudaFuncAttributeMaxDynamicSharedMemorySize, SM_TOTAL);
    score_kernel<<<NBLOCKS, NTHREADS, SM_TOTAL>>>(action_ids, emb, b2);

    norm_kernel<<<(A_SIZE + 255) / 256, 256>>>(out);
}

// round 7
// speedup vs baseline: 4.0207x; 1.1014x over previous
#include <cuda_runtime.h>
#include <cuda_bf16.h>
#include <cstdint>

#define A_SIZE   100000
#define D_DIM    128
#define L_TOK    64
#define TILE_A   128
#define NBLOCKS  148
#define NTILES   ((A_SIZE + TILE_A - 1) / TILE_A)
#define NTHREADS 256

// ---------------- smem layout (bytes) ----------------
#define SM_RELH  0                     // [128 rows][256B] bf16, xor-swizzled (A operand)
#define SM_RELL  (SM_RELH + 32768)
#define SM_QTH   (SM_RELL + 32768)     // [64 t-rows][256B]  Qt[t][d]   (B, n-major)
#define SM_QTL   (SM_QTH + 16384)
#define SM_MH    (SM_QTL + 16384)      // [128 j-rows][128B] M stored [j][l]
#define SM_ML    (SM_MH + 16384)
#define SM_W2H   (SM_ML + 16384)       // [128 j-rows][256B] W2 stored [j][d]
#define SM_W2L   (SM_W2H + 32768)
#define SM_H1    (SM_W2L + 32768)      // f32 [128]
#define SM_B2    (SM_H1 + 512)         // f32 [128]
#define SM_DB2   (SM_B2 + 512)         // f32 [256]
#define SM_RM    (SM_DB2 + 1024)       // f32 [8]
#define SM_RZ    (SM_RM + 32)          // f32 [8]
#define SM_FLAG  (SM_RZ + 32)          // int
#define SM_TOTAL (SM_FLAG + 16)

// ---------------- device scratch ----------------
__device__ __align__(16) float g_scores[A_SIZE];
__device__ __align__(16) float g_h1pre[D_DIM];
__device__ __align__(16) float g_stats[2];
__device__ __align__(16) float g_pmax[256];
__device__ __align__(16) float g_psum[256];
__device__ int g_done;
__device__ int g_flag;
__device__ __align__(16) uint16_t g_qt_hi[L_TOK * D_DIM];   // [t][d]
__device__ __align__(16) uint16_t g_qt_lo[L_TOK * D_DIM];
__device__ __align__(16) uint16_t g_m_hi[D_DIM * L_TOK];    // [j][l]
__device__ __align__(16) uint16_t g_m_lo[D_DIM * L_TOK];
__device__ __align__(16) uint16_t g_w2_hi[D_DIM * D_DIM];   // [j][d] = W2[d][j]
__device__ __align__(16) uint16_t g_w2_lo[D_DIM * D_DIM];

// ---------------- helpers ----------------
__device__ __forceinline__ uint16_t bf16_bits(float x) {
    __nv_bfloat16 h = __float2bfloat16(x);
    return *reinterpret_cast<uint16_t*>(&h);
}
__device__ __forceinline__ float bf16_val(uint16_t b) {
    __nv_bfloat16 h = *reinterpret_cast<__nv_bfloat16*>(&b);
    return __bfloat162float(h);
}
__device__ __forceinline__ void split_pack(float x, float y, uint32_t& hp, uint32_t& lp) {
    uint16_t hx = bf16_bits(x), hy = bf16_bits(y);
    uint16_t lx = bf16_bits(x - bf16_val(hx)), ly = bf16_bits(y - bf16_val(hy));
    hp = ((uint32_t)hy << 16) | hx;
    lp = ((uint32_t)ly << 16) | lx;
}
__device__ __forceinline__ uint32_t smem_u32(const void* p) {
    uint32_t a;
    asm("{ .reg .u64 t; cvta.to.shared.u64 t, %1; cvt.u32.u64 %0, t; }" : "=r"(a) : "l"(p));
    return a;
}
__device__ __forceinline__ void ldm4(uint32_t (&r)[4], uint32_t addr) {
    asm volatile("ldmatrix.sync.aligned.m8n8.x4.shared.b16 {%0,%1,%2,%3}, [%4];"
                 : "=r"(r[0]), "=r"(r[1]), "=r"(r[2]), "=r"(r[3]) : "r"(addr));
}
__device__ __forceinline__ void mma16816(float (&c)[4], const uint32_t (&a)[4],
                                         uint32_t b0, uint32_t b1) {
    asm volatile(
        "mma.sync.aligned.m16n8k16.row.col.f32.bf16.bf16.f32 "
        "{%0,%1,%2,%3}, {%4,%5,%6,%7}, {%8,%9}, {%0,%1,%2,%3};"
        : "+f"(c[0]), "+f"(c[1]), "+f"(c[2]), "+f"(c[3])
        : "r"(a[0]), "r"(a[1]), "r"(a[2]), "r"(a[3]), "r"(b0), "r"(b1));
}
__device__ __forceinline__ void oz_merge(float& m, float& z, float om, float oz) {
    float nm = fmaxf(m, om);
    z = z * __expf(m - nm) + oz * __expf(om - nm);
    m = nm;
}

// ---------------- fast prep kernel ----------------
// blocks 0..63   : M[j][l] for j = 2b, 2b+1  (256 thr: 2j x 64l x 2 k-halves)
// blocks 64..127 : W2 split, 256 elems each
// blocks 128..159: Qt split, 256 elems each
// block  160     : h1pre + flag reset
__global__ __launch_bounds__(256, 1)
void prep_all(const float* __restrict__ W1, const float* __restrict__ b1,
              const float* __restrict__ Qt, const float* __restrict__ hist,
              const float* __restrict__ W2) {
    const int b = blockIdx.x, tid = threadIdx.x;
    if (b < 64) {
        // M[j][l] = sum_k W1[j][128+k] * Qt[l][k]
        const int jsub = tid >> 7;           // 0..1
        const int l    = (tid >> 1) & 63;    // 0..63
        const int kh   = tid & 1;            // k half
        const int j    = b * 2 + jsub;
        const float4* w4 = (const float4*)(W1 + j * 2 * D_DIM + D_DIM + kh * 64);
        const float4* q4 = (const float4*)(Qt + l * D_DIM + kh * 64);
        float a0 = 0.f, a1 = 0.f, a2 = 0.f, a3 = 0.f;
        #pragma unroll
        for (int i = 0; i < 16; i += 4) {
            float4 w0 = w4[i],     q0 = q4[i];
            float4 w1v = w4[i + 1], q1 = q4[i + 1];
            float4 w2v = w4[i + 2], q2 = q4[i + 2];
            float4 w3 = w4[i + 3], q3 = q4[i + 3];
            a0 += w0.x * q0.x + w0.y * q0.y + w0.z * q0.z + w0.w * q0.w;
            a1 += w1v.x * q1.x + w1v.y * q1.y + w1v.z * q1.z + w1v.w * q1.w;
            a2 += w2v.x * q2.x + w2v.y * q2.y + w2v.z * q2.z + w2v.w * q2.w;
            a3 += w3.x * q3.x + w3.y * q3.y + w3.z * q3.z + w3.w * q3.w;
        }
        float acc = (a0 + a1) + (a2 + a3);
        acc += __shfl_xor_sync(0xFFFFFFFFu, acc, 1);   // combine k-halves
        if (kh == 0) {
            uint16_t mh = bf16_bits(acc);
            g_m_hi[j * L_TOK + l] = mh;
            g_m_lo[j * L_TOK + l] = bf16_bits(acc - bf16_val(mh));
        }
    } else if (b < 128) {
        // W2 split (transposed store): elems (b-64)*256 + tid
        int i = (b - 64) * 256 + tid;        // i = d*128 + j
        int d = i >> 7, j = i & 127;
        float x = W2[i];
        uint16_t h = bf16_bits(x);
        g_w2_hi[j * D_DIM + d] = h;
        g_w2_lo[j * D_DIM + d] = bf16_bits(x - bf16_val(h));
    } else if (b < 160) {
        int i = (b - 128) * 256 + tid;
        float x = Qt[i];
        uint16_t h = bf16_bits(x);
        g_qt_hi[i] = h;
        g_qt_lo[i] = bf16_bits(x - bf16_val(h));
    } else {
        // h1pre: j = tid>>1, k-half = tid&1
        const int j = tid >> 1, kh = tid & 1;
        const float4* w4 = (const float4*)(W1 + j * 2 * D_DIM + kh * 64);
        const float4* h4 = (const float4*)(hist + kh * 64);
        float a0 = 0.f, a1 = 0.f;
        #pragma unroll
        for (int i = 0; i < 16; i += 2) {
            float4 w0 = w4[i], q0 = h4[i];
            float4 w1v = w4[i + 1], q1 = h4[i + 1];
            a0 += w0.x * q0.x + w0.y * q0.y + w0.z * q0.z + w0.w * q0.w;
            a1 += w1v.x * q1.x + w1v.y * q1.y + w1v.z * q1.z + w1v.w * q1.w;
        }
        float acc = a0 + a1;
        acc += __shfl_xor_sync(0xFFFFFFFFu, acc, 1);
        if (kh == 0) g_h1pre[j] = acc + b1[j];
        if (tid == 0) { g_done = 0; g_flag = 0; }
    }
}

// ---------------- main score kernel (+ fused softmax + normalize) ----------------
__global__ __launch_bounds__(NTHREADS, 1)
void score_kernel(const int* __restrict__ ids_g,
                  const float* __restrict__ emb,
                  const float* __restrict__ b2_g,
                  float* __restrict__ out) {
    extern __shared__ char smem[];
    const int tid  = threadIdx.x;
    const int wid  = tid >> 5;
    const int lane = tid & 31;
    const int q    = lane & 3;
    const int nidx = lane >> 2;

    float* s_h1  = (float*)(smem + SM_H1);
    float* s_b2  = (float*)(smem + SM_B2);
    float* s_db2 = (float*)(smem + SM_DB2);
    float* s_rm  = (float*)(smem + SM_RM);
    float* s_rz  = (float*)(smem + SM_RZ);
    int*   s_fl  = (int*)(smem + SM_FLAG);
    const uint32_t sb32 = smem_u32(smem);

    // ---- one-time fills (swizzled 16B chunks; row-major n x k) ----
    if (tid < 128) { s_h1[tid] = g_h1pre[tid]; s_b2[tid] = b2_g[tid]; }
    {
        const uint4* qh = (const uint4*)g_qt_hi;
        const uint4* ql = (const uint4*)g_qt_lo;
        for (int i = tid; i < 64 * 16; i += NTHREADS) {
            int r = i >> 4, c = i & 15;
            int o = r * 256 + ((c * 16) ^ ((r & 7) << 4));
            *(uint4*)(smem + SM_QTH + o) = qh[i];
            *(uint4*)(smem + SM_QTL + o) = ql[i];
        }
        const uint4* mh = (const uint4*)g_m_hi;
        const uint4* ml = (const uint4*)g_m_lo;
        for (int i = tid; i < 128 * 8; i += NTHREADS) {
            int r = i >> 3, c = i & 7;
            int o = r * 128 + ((c * 16) ^ ((r & 7) << 4));
            *(uint4*)(smem + SM_MH + o) = mh[i];
            *(uint4*)(smem + SM_ML + o) = ml[i];
        }
        const uint4* wh = (const uint4*)g_w2_hi;
        const uint4* wl = (const uint4*)g_w2_lo;
        for (int i = tid; i < 128 * 16; i += NTHREADS) {
            int r = i >> 4, c = i & 15;
            int o = r * 256 + ((c * 16) ^ ((r & 7) << 4));
            *(uint4*)(smem + SM_W2H + o) = wh[i];
            *(uint4*)(smem + SM_W2L + o) = wl[i];
        }
    }
    __syncthreads();

    const int lrow = lane & 7;
    const int lgrp = lane >> 3;
    const int nadd = (lgrp & 2) << 2;
    const int cpar = lgrp & 1;
    const int lr4  = lrow << 4;
    const uint32_t qtB  = sb32 + SM_QTH + (uint32_t)((nadd + lrow) * 256);
    const uint32_t qtBl = sb32 + SM_QTL + (uint32_t)((nadd + lrow) * 256);
    const uint32_t mB   = sb32 + SM_MH  + (uint32_t)((nadd + lrow) * 128);
    const uint32_t mBl  = sb32 + SM_ML  + (uint32_t)((nadd + lrow) * 128);
    const uint32_t w2B  = sb32 + SM_W2H + (uint32_t)((nadd + lrow) * 256);
    const uint32_t w2Bl = sb32 + SM_W2L + (uint32_t)((nadd + lrow) * 256);

    const float4* emb4 = (const float4*)emb;

    float lm = -1e30f, lz = 0.f;

    for (int tile = blockIdx.x; tile < NTILES; tile += gridDim.x) {
        // ================= gather rel -> swizzled smem (hi/lo) =================
        {
            const int row = tid >> 1;
            const int a   = tile * TILE_A + row;
            const int id  = (a < A_SIZE) ? ids_g[a] : 0;
            const float4* r4 = emb4 + (size_t)id * 32;
            float4 v[16];
            #pragma unroll
            for (int i = 0; i < 8; i++) {
                const int c = 2 * i + (tid & 1);
                v[2 * i]     = r4[c * 2];
                v[2 * i + 1] = r4[c * 2 + 1];
            }
            float db2 = 0.f;
            #pragma unroll
            for (int i = 0; i < 8; i++) {
                const int c = 2 * i + (tid & 1);
                float4 v0 = v[2 * i], v1 = v[2 * i + 1];
                const float* bb = s_b2 + c * 8;
                db2 += v0.x * bb[0] + v0.y * bb[1] + v0.z * bb[2] + v0.w * bb[3]
                     + v1.x * bb[4] + v1.y * bb[5] + v1.z * bb[6] + v1.w * bb[7];
                uint4 hi, lo;
                split_pack(v0.x, v0.y, hi.x, lo.x);
                split_pack(v0.z, v0.w, hi.y, lo.y);
                split_pack(v1.x, v1.y, hi.z, lo.z);
                split_pack(v1.z, v1.w, hi.w, lo.w);
                const int b = (c * 16) ^ ((row & 7) << 4);
                *(uint4*)(smem + SM_RELH + row * 256 + b) = hi;
                *(uint4*)(smem + SM_RELL + row * 256 + b) = lo;
            }
            s_db2[tid] = db2;
        }
        __syncthreads();

        // ================= rel A-fragments =================
        uint32_t Ah[8][4], Al[8][4];
        {
            const int rowa = 16 * wid + (lane & 15);
            const int kh   = ((lane >> 4) & 1) << 4;
            #pragma unroll
            for (int kt = 0; kt < 8; kt++) {
                const int b = (kt * 32 + kh) ^ ((rowa & 7) << 4);
                ldm4(Ah[kt], sb32 + SM_RELH + rowa * 256 + b);
                ldm4(Al[kt], sb32 + SM_RELL + rowa * 256 + b);
            }
        }

        // ================= stage B: att = rel . QtT =================
        float catt[8][4];
        #pragma unroll
        for (int nt = 0; nt < 8; nt++)
            #pragma unroll
            for (int x = 0; x < 4; x++) catt[nt][x] = 0.f;

        #pragma unroll
        for (int kt = 0; kt < 8; kt++) {
            const uint32_t swz = (uint32_t)((((kt * 2 + cpar) * 16)) ^ lr4);
            #pragma unroll
            for (int np = 0; np < 4; np++) {
                uint32_t bh[4], bl[4];
                ldm4(bh, qtB  + np * 4096 + swz);
                ldm4(bl, qtBl + np * 4096 + swz);
                mma16816(catt[2 * np],     Ah[kt], bh[0], bh[1]);
                mma16816(catt[2 * np],     Al[kt], bh[0], bh[1]);
                mma16816(catt[2 * np],     Ah[kt], bl[0], bl[1]);
                mma16816(catt[2 * np + 1], Ah[kt], bh[2], bh[3]);
                mma16816(catt[2 * np + 1], Al[kt], bh[2], bh[3]);
                mma16816(catt[2 * np + 1], Ah[kt], bl[2], bl[3]);
            }
        }

        // ================= softmax in fragments =================
        uint32_t Wh[4][4], Wl[4][4];
        {
            float m0 = -1e30f, m1 = -1e30f;
            #pragma unroll
            for (int nt = 0; nt < 8; nt++) {
                m0 = fmaxf(m0, fmaxf(catt[nt][0], catt[nt][1]));
                m1 = fmaxf(m1, fmaxf(catt[nt][2], catt[nt][3]));
            }
            m0 = fmaxf(m0, __shfl_xor_sync(0xFFFFFFFFu, m0, 1));
            m0 = fmaxf(m0, __shfl_xor_sync(0xFFFFFFFFu, m0, 2));
            m1 = fmaxf(m1, __shfl_xor_sync(0xFFFFFFFFu, m1, 1));
            m1 = fmaxf(m1, __shfl_xor_sync(0xFFFFFFFFu, m1, 2));
            float s0 = 0.f, s1 = 0.f;
            #pragma unroll
            for (int nt = 0; nt < 8; nt++) {
                catt[nt][0] = __expf(catt[nt][0] - m0);
                catt[nt][1] = __expf(catt[nt][1] - m0);
                catt[nt][2] = __expf(catt[nt][2] - m1);
                catt[nt][3] = __expf(catt[nt][3] - m1);
                s0 += catt[nt][0] + catt[nt][1];
                s1 += catt[nt][2] + catt[nt][3];
            }
            s0 += __shfl_xor_sync(0xFFFFFFFFu, s0, 1);
            s0 += __shfl_xor_sync(0xFFFFFFFFu, s0, 2);
            s1 += __shfl_xor_sync(0xFFFFFFFFu, s1, 1);
            s1 += __shfl_xor_sync(0xFFFFFFFFu, s1, 2);
            const float i0 = 1.f / s0, i1 = 1.f / s1;
            #pragma unroll
            for (int j = 0; j < 4; j++) {
                split_pack(catt[2 * j][0] * i0, catt[2 * j][1] * i0, Wh[j][0], Wl[j][0]);
                split_pack(catt[2 * j][2] * i1, catt[2 * j][3] * i1, Wh[j][1], Wl[j][1]);
                split_pack(catt[2 * j + 1][0] * i0, catt[2 * j + 1][1] * i0, Wh[j][2], Wl[j][2]);
                split_pack(catt[2 * j + 1][2] * i1, catt[2 * j + 1][3] * i1, Wh[j][3], Wl[j][3]);
            }
        }

        // ================= fused stages C & D + epilogue =================
        float sc0 = 0.f, sc1 = 0.f;
        #pragma unroll
        for (int np = 0; np < 8; np++) {
            float cc0[4] = {0.f, 0.f, 0.f, 0.f};
            float cc1[4] = {0.f, 0.f, 0.f, 0.f};
            float cv0[4] = {0.f, 0.f, 0.f, 0.f};
            float cv1[4] = {0.f, 0.f, 0.f, 0.f};
            #pragma unroll
            for (int kt = 0; kt < 4; kt++) {
                const uint32_t swz = (uint32_t)((((kt * 2 + cpar) * 16)) ^ lr4);
                uint32_t bh[4], bl[4];
                ldm4(bh, mB  + np * 2048 + swz);
                ldm4(bl, mBl + np * 2048 + swz);
                mma16816(cc0, Wh[kt], bh[0], bh[1]);
                mma16816(cc0, Wl[kt], bh[0], bh[1]);
                mma16816(cc0, Wh[kt], bl[0], bl[1]);
                mma16816(cc1, Wh[kt], bh[2], bh[3]);
                mma16816(cc1, Wl[kt], bh[2], bh[3]);
                mma16816(cc1, Wh[kt], bl[2], bl[3]);
            }
            #pragma unroll
            for (int kt = 0; kt < 8; kt++) {
                const uint32_t swz = (uint32_t)((((kt * 2 + cpar) * 16)) ^ lr4);
                uint32_t bh[4], bl[4];
                ldm4(bh, w2B  + np * 4096 + swz);
                ldm4(bl, w2Bl + np * 4096 + swz);
                mma16816(cv0, Ah[kt], bh[0], bh[1]);
                mma16816(cv0, Al[kt], bh[0], bh[1]);
                mma16816(cv0, Ah[kt], bl[0], bl[1]);
                mma16816(cv1, Ah[kt], bh[2], bh[3]);
                mma16816(cv1, Al[kt], bh[2], bh[3]);
                mma16816(cv1, Ah[kt], bl[2], bl[3]);
            }
            {
                const int j0 = (2 * np) * 8 + 2 * q;
                const float h1a = s_h1[j0], h1b = s_h1[j0 + 1];
                sc0 += fmaxf(cc0[0] + h1a, 0.f) * cv0[0] + fmaxf(cc0[1] + h1b, 0.f) * cv0[1];
                sc1 += fmaxf(cc0[2] + h1a, 0.f) * cv0[2] + fmaxf(cc0[3] + h1b, 0.f) * cv0[3];
            }
            {
                const int j0 = (2 * np + 1) * 8 + 2 * q;
                const float h1a = s_h1[j0], h1b = s_h1[j0 + 1];
                sc0 += fmaxf(cc1[0] + h1a, 0.f) * cv1[0] + fmaxf(cc1[1] + h1b, 0.f) * cv1[1];
                sc1 += fmaxf(cc1[2] + h1a, 0.f) * cv1[2] + fmaxf(cc1[3] + h1b, 0.f) * cv1[3];
            }
        }

        sc0 += __shfl_xor_sync(0xFFFFFFFFu, sc0, 1);
        sc0 += __shfl_xor_sync(0xFFFFFFFFu, sc0, 2);
        sc1 += __shfl_xor_sync(0xFFFFFFFFu, sc1, 1);
        sc1 += __shfl_xor_sync(0xFFFFFFFFu, sc1, 2);
        if (q == 0) {
            const int r0 = 16 * wid + nidx;
            const int r1 = r0 + 8;
            const int a0 = tile * TILE_A + r0;
            const int a1 = tile * TILE_A + r1;
            if (a0 < A_SIZE) {
                float s = sc0 + s_db2[2 * r0] + s_db2[2 * r0 + 1];
                g_scores[a0] = s;
                float nm = fmaxf(lm, s);
                lz = lz * __expf(lm - nm) + __expf(s - nm);
                lm = nm;
            }
            if (a1 < A_SIZE) {
                float s = sc1 + s_db2[2 * r1] + s_db2[2 * r1 + 1];
                g_scores[a1] = s;
                float nm = fmaxf(lm, s);
                lz = lz * __expf(lm - nm) + __expf(s - nm);
                lm = nm;
            }
        }
        __syncthreads();
    }

    // ================= fused global softmax reduction =================
    #pragma unroll
    for (int o = 16; o > 0; o >>= 1) {
        float om = __shfl_xor_sync(0xFFFFFFFFu, lm, o);
        float oz = __shfl_xor_sync(0xFFFFFFFFu, lz, o);
        oz_merge(lm, lz, om, oz);
    }
    if (lane == 0) { s_rm[wid] = lm; s_rz[wid] = lz; }
    __syncthreads();
    if (tid == 0) {
        float M = s_rm[0], Z = s_rz[0];
        #pragma unroll
        for (int w = 1; w < 8; w++) oz_merge(M, Z, s_rm[w], s_rz[w]);
        g_pmax[blockIdx.x] = M;
        g_psum[blockIdx.x] = Z;
        __threadfence();
        int old = atomicAdd(&g_done, 1);
        s_fl[0] = (old == (int)gridDim.x - 1) ? 1 : 0;
    }
    __syncthreads();
    if (s_fl[0]) {
        if (wid == 0) {
            float M = -1e30f, Z = 0.f;
            for (int i = lane; i < (int)gridDim.x; i += 32)
                oz_merge(M, Z, g_pmax[i], g_psum[i]);
            #pragma unroll
            for (int o = 16; o > 0; o >>= 1) {
                float om = __shfl_xor_sync(0xFFFFFFFFu, M, o);
                float oz = __shfl_xor_sync(0xFFFFFFFFu, Z, o);
                oz_merge(M, Z, om, oz);
            }
            if (lane == 0) {
                g_stats[0] = M; g_stats[1] = Z;
                __threadfence();
                atomicExch(&g_flag, 1);
            }
        }
    } else if (tid == 0) {
        // spin until stats published (all 148 CTAs resident -> no deadlock)
        while (atomicAdd(&g_flag, 0) == 0) { __nanosleep(64); }
    }
    __syncthreads();

    // ================= fused normalize =================
    {
        const float gm  = g_stats[0];
        const float inv = 1.f / g_stats[1];
        for (int i = blockIdx.x * NTHREADS + tid; i < A_SIZE; i += gridDim.x * NTHREADS)
            out[i] = __expf(g_scores[i] - gm) * inv;
    }
}

// ---------------- launch ----------------
extern "C" void kernel_launch(void* const* d_in, const int* in_sizes, int n_in,
                              void* d_out, int out_size) {
    const int*   action_ids = (const int*)d_in[0];
    const float* emb        = (const float*)d_in[1];
    const float* question_t = (const float*)d_in[2];
    const float* history_t  = (const float*)d_in[3];
    const float* W1         = (const float*)d_in[4];
    const float* b1         = (const float*)d_in[5];
    const float* W2         = (const float*)d_in[6];
    const float* b2         = (const float*)d_in[7];
    float* out = (float*)d_out;

    prep_all<<<161, 256>>>(W1, b1, question_t, history_t, W2);

    cudaFuncSetAttribute(score_kernel,
                         cudaFuncAttributeMaxDynamicSharedMemorySize, SM_TOTAL);
    score_kernel<<<NBLOCKS, NTHREADS, SM_TOTAL>>>(action_ids, emb, b2, out);
}

// round 8
// speedup vs baseline: 4.1236x; 1.0256x over previous
#include <cuda_runtime.h>
#include <cuda_bf16.h>
#include <cstdint>

#define A_SIZE   100000
#define D_DIM    128
#define L_TOK    64
#define TILE_A   176
#define NBLOCKS  148
#define NTILES   ((A_SIZE + TILE_A - 1) / TILE_A)
#define NTHREADS 352
#define NWARPS   11

// ---------------- smem layout (bytes) ----------------
#define SM_RELH  0                       // [176 rows][256B] bf16, xor-swizzled (A operand)
#define SM_RELL  (SM_RELH + 45056)
#define SM_QTH   (SM_RELL + 45056)       // [64 t-rows][256B]  Qt[t][d]   (B, n-major)
#define SM_QTL   (SM_QTH + 16384)
#define SM_MH    (SM_QTL + 16384)        // [128 j-rows][128B] M stored [j][l]
#define SM_ML    (SM_MH + 16384)
#define SM_W2H   (SM_ML + 16384)         // [128 j-rows][256B] W2 stored [j][d]
#define SM_W2L   (SM_W2H + 32768)
#define SM_H1    (SM_W2L + 32768)        // f32 [128]
#define SM_B2    (SM_H1 + 512)           // f32 [128]
#define SM_DB2   (SM_B2 + 512)           // f32 [352]
#define SM_RM    (SM_DB2 + 1472)         // f32 [16]
#define SM_RZ    (SM_RM + 64)            // f32 [16]
#define SM_FLAG  (SM_RZ + 64)            // int
#define SM_TOTAL (SM_FLAG + 16)

// ---------------- device scratch ----------------
__device__ __align__(16) float g_scores[A_SIZE];
__device__ __align__(16) float g_h1pre[D_DIM];
__device__ __align__(16) float g_stats[2];
__device__ __align__(16) float g_pmax[256];
__device__ __align__(16) float g_psum[256];
__device__ int g_done;
__device__ int g_flag;
__device__ __align__(16) uint16_t g_qt_hi[L_TOK * D_DIM];   // [t][d]
__device__ __align__(16) uint16_t g_qt_lo[L_TOK * D_DIM];
__device__ __align__(16) uint16_t g_m_hi[D_DIM * L_TOK];    // [j][l]
__device__ __align__(16) uint16_t g_m_lo[D_DIM * L_TOK];
__device__ __align__(16) uint16_t g_w2_hi[D_DIM * D_DIM];   // [j][d] = W2[d][j]
__device__ __align__(16) uint16_t g_w2_lo[D_DIM * D_DIM];

// ---------------- helpers ----------------
__device__ __forceinline__ uint16_t bf16_bits(float x) {
    __nv_bfloat16 h = __float2bfloat16(x);
    return *reinterpret_cast<uint16_t*>(&h);
}
__device__ __forceinline__ float bf16_val(uint16_t b) {
    __nv_bfloat16 h = *reinterpret_cast<__nv_bfloat16*>(&b);
    return __bfloat162float(h);
}
__device__ __forceinline__ void split_pack(float x, float y, uint32_t& hp, uint32_t& lp) {
    uint16_t hx = bf16_bits(x), hy = bf16_bits(y);
    uint16_t lx = bf16_bits(x - bf16_val(hx)), ly = bf16_bits(y - bf16_val(hy));
    hp = ((uint32_t)hy << 16) | hx;
    lp = ((uint32_t)ly << 16) | lx;
}
__device__ __forceinline__ uint32_t smem_u32(const void* p) {
    uint32_t a;
    asm("{ .reg .u64 t; cvta.to.shared.u64 t, %1; cvt.u32.u64 %0, t; }" : "=r"(a) : "l"(p));
    return a;
}
__device__ __forceinline__ void ldm4(uint32_t (&r)[4], uint32_t addr) {
    asm volatile("ldmatrix.sync.aligned.m8n8.x4.shared.b16 {%0,%1,%2,%3}, [%4];"
                 : "=r"(r[0]), "=r"(r[1]), "=r"(r[2]), "=r"(r[3]) : "r"(addr));
}
__device__ __forceinline__ void mma16816(float (&c)[4], const uint32_t (&a)[4],
                                         uint32_t b0, uint32_t b1) {
    asm volatile(
        "mma.sync.aligned.m16n8k16.row.col.f32.bf16.bf16.f32 "
        "{%0,%1,%2,%3}, {%4,%5,%6,%7}, {%8,%9}, {%0,%1,%2,%3};"
        : "+f"(c[0]), "+f"(c[1]), "+f"(c[2]), "+f"(c[3])
        : "r"(a[0]), "r"(a[1]), "r"(a[2]), "r"(a[3]), "r"(b0), "r"(b1));
}
__device__ __forceinline__ void oz_merge(float& m, float& z, float om, float oz) {
    float nm = fmaxf(m, om);
    z = z * __expf(m - nm) + oz * __expf(om - nm);
    m = nm;
}

// ---------------- fast prep kernel ----------------
__global__ __launch_bounds__(256, 1)
void prep_all(const float* __restrict__ W1, const float* __restrict__ b1,
              const float* __restrict__ Qt, const float* __restrict__ hist,
              const float* __restrict__ W2) {
    const int b = blockIdx.x, tid = threadIdx.x;
    if (b < 64) {
        const int jsub = tid >> 7;
        const int l    = (tid >> 1) & 63;
        const int kh   = tid & 1;
        const int j    = b * 2 + jsub;
        const float4* w4 = (const float4*)(W1 + j * 2 * D_DIM + D_DIM + kh * 64);
        const float4* q4 = (const float4*)(Qt + l * D_DIM + kh * 64);
        float a0 = 0.f, a1 = 0.f, a2 = 0.f, a3 = 0.f;
        #pragma unroll
        for (int i = 0; i < 16; i += 4) {
            float4 w0 = w4[i],     q0 = q4[i];
            float4 w1v = w4[i + 1], q1 = q4[i + 1];
            float4 w2v = w4[i + 2], q2 = q4[i + 2];
            float4 w3 = w4[i + 3], q3 = q4[i + 3];
            a0 += w0.x * q0.x + w0.y * q0.y + w0.z * q0.z + w0.w * q0.w;
            a1 += w1v.x * q1.x + w1v.y * q1.y + w1v.z * q1.z + w1v.w * q1.w;
            a2 += w2v.x * q2.x + w2v.y * q2.y + w2v.z * q2.z + w2v.w * q2.w;
            a3 += w3.x * q3.x + w3.y * q3.y + w3.z * q3.z + w3.w * q3.w;
        }
        float acc = (a0 + a1) + (a2 + a3);
        acc += __shfl_xor_sync(0xFFFFFFFFu, acc, 1);
        if (kh == 0) {
            uint16_t mh = bf16_bits(acc);
            g_m_hi[j * L_TOK + l] = mh;
            g_m_lo[j * L_TOK + l] = bf16_bits(acc - bf16_val(mh));
        }
    } else if (b < 128) {
        int i = (b - 64) * 256 + tid;        // i = d*128 + j
        int d = i >> 7, j = i & 127;
        float x = W2[i];
        uint16_t h = bf16_bits(x);
        g_w2_hi[j * D_DIM + d] = h;
        g_w2_lo[j * D_DIM + d] = bf16_bits(x - bf16_val(h));
    } else if (b < 160) {
        int i = (b - 128) * 256 + tid;
        float x = Qt[i];
        uint16_t h = bf16_bits(x);
        g_qt_hi[i] = h;
        g_qt_lo[i] = bf16_bits(x - bf16_val(h));
    } else {
        const int j = tid >> 1, kh = tid & 1;
        const float4* w4 = (const float4*)(W1 + j * 2 * D_DIM + kh * 64);
        const float4* h4 = (const float4*)(hist + kh * 64);
        float a0 = 0.f, a1 = 0.f;
        #pragma unroll
        for (int i = 0; i < 16; i += 2) {
            float4 w0 = w4[i], q0 = h4[i];
            float4 w1v = w4[i + 1], q1 = h4[i + 1];
            a0 += w0.x * q0.x + w0.y * q0.y + w0.z * q0.z + w0.w * q0.w;
            a1 += w1v.x * q1.x + w1v.y * q1.y + w1v.z * q1.z + w1v.w * q1.w;
        }
        float acc = a0 + a1;
        acc += __shfl_xor_sync(0xFFFFFFFFu, acc, 1);
        if (kh == 0) g_h1pre[j] = acc + b1[j];
        if (tid == 0) { g_done = 0; g_flag = 0; }
    }
}

// ---------------- main score kernel (+ fused softmax + normalize) ----------------
__global__ __launch_bounds__(NTHREADS, 1)
void score_kernel(const int* __restrict__ ids_g,
                  const float* __restrict__ emb,
                  const float* __restrict__ b2_g,
                  float* __restrict__ out) {
    extern __shared__ char smem[];
    const int tid  = threadIdx.x;
    const int wid  = tid >> 5;
    const int lane = tid & 31;
    const int q    = lane & 3;
    const int nidx = lane >> 2;

    float* s_h1  = (float*)(smem + SM_H1);
    float* s_b2  = (float*)(smem + SM_B2);
    float* s_db2 = (float*)(smem + SM_DB2);
    float* s_rm  = (float*)(smem + SM_RM);
    float* s_rz  = (float*)(smem + SM_RZ);
    int*   s_fl  = (int*)(smem + SM_FLAG);
    const uint32_t sb32 = smem_u32(smem);

    // ---- one-time fills (swizzled 16B chunks; row-major n x k) ----
    if (tid < 128) { s_h1[tid] = g_h1pre[tid]; s_b2[tid] = b2_g[tid]; }
    {
        const uint4* qh = (const uint4*)g_qt_hi;
        const uint4* ql = (const uint4*)g_qt_lo;
        for (int i = tid; i < 64 * 16; i += NTHREADS) {
            int r = i >> 4, c = i & 15;
            int o = r * 256 + ((c * 16) ^ ((r & 7) << 4));
            *(uint4*)(smem + SM_QTH + o) = qh[i];
            *(uint4*)(smem + SM_QTL + o) = ql[i];
        }
        const uint4* mh = (const uint4*)g_m_hi;
        const uint4* ml = (const uint4*)g_m_lo;
        for (int i = tid; i < 128 * 8; i += NTHREADS) {
            int r = i >> 3, c = i & 7;
            int o = r * 128 + ((c * 16) ^ ((r & 7) << 4));
            *(uint4*)(smem + SM_MH + o) = mh[i];
            *(uint4*)(smem + SM_ML + o) = ml[i];
        }
        const uint4* wh = (const uint4*)g_w2_hi;
        const uint4* wl = (const uint4*)g_w2_lo;
        for (int i = tid; i < 128 * 16; i += NTHREADS) {
            int r = i >> 4, c = i & 15;
            int o = r * 256 + ((c * 16) ^ ((r & 7) << 4));
            *(uint4*)(smem + SM_W2H + o) = wh[i];
            *(uint4*)(smem + SM_W2L + o) = wl[i];
        }
    }
    __syncthreads();

    const int lrow = lane & 7;
    const int lgrp = lane >> 3;
    const int nadd = (lgrp & 2) << 2;
    const int cpar = lgrp & 1;
    const int lr4  = lrow << 4;
    const uint32_t qtB  = sb32 + SM_QTH + (uint32_t)((nadd + lrow) * 256);
    const uint32_t qtBl = sb32 + SM_QTL + (uint32_t)((nadd + lrow) * 256);
    const uint32_t mB   = sb32 + SM_MH  + (uint32_t)((nadd + lrow) * 128);
    const uint32_t mBl  = sb32 + SM_ML  + (uint32_t)((nadd + lrow) * 128);
    const uint32_t w2B  = sb32 + SM_W2H + (uint32_t)((nadd + lrow) * 256);
    const uint32_t w2Bl = sb32 + SM_W2L + (uint32_t)((nadd + lrow) * 256);

    const float4* emb4 = (const float4*)emb;

    float lm = -1e30f, lz = 0.f;

    for (int tile = blockIdx.x; tile < NTILES; tile += gridDim.x) {
        // ================= gather rel -> swizzled smem (hi/lo) =================
        {
            const int row = tid >> 1;
            const int a   = tile * TILE_A + row;
            const int id  = (a < A_SIZE) ? ids_g[a] : 0;
            const float4* r4 = emb4 + (size_t)id * 32;
            float4 v[16];
            #pragma unroll
            for (int i = 0; i < 8; i++) {
                const int c = 2 * i + (tid & 1);
                v[2 * i]     = r4[c * 2];
                v[2 * i + 1] = r4[c * 2 + 1];
            }
            float db2 = 0.f;
            #pragma unroll
            for (int i = 0; i < 8; i++) {
                const int c = 2 * i + (tid & 1);
                float4 v0 = v[2 * i], v1 = v[2 * i + 1];
                const float* bb = s_b2 + c * 8;
                db2 += v0.x * bb[0] + v0.y * bb[1] + v0.z * bb[2] + v0.w * bb[3]
                     + v1.x * bb[4] + v1.y * bb[5] + v1.z * bb[6] + v1.w * bb[7];
                uint4 hi, lo;
                split_pack(v0.x, v0.y, hi.x, lo.x);
                split_pack(v0.z, v0.w, hi.y, lo.y);
                split_pack(v1.x, v1.y, hi.z, lo.z);
                split_pack(v1.z, v1.w, hi.w, lo.w);
                const int b = (c * 16) ^ ((row & 7) << 4);
                *(uint4*)(smem + SM_RELH + row * 256 + b) = hi;
                *(uint4*)(smem + SM_RELL + row * 256 + b) = lo;
            }
            s_db2[tid] = db2;
        }
        __syncthreads();

        // ================= rel A-fragments =================
        uint32_t Ah[8][4], Al[8][4];
        {
            const int rowa = 16 * wid + (lane & 15);
            const int kh   = ((lane >> 4) & 1) << 4;
            #pragma unroll
            for (int kt = 0; kt < 8; kt++) {
                const int b = (kt * 32 + kh) ^ ((rowa & 7) << 4);
                ldm4(Ah[kt], sb32 + SM_RELH + rowa * 256 + b);
                ldm4(Al[kt], sb32 + SM_RELL + rowa * 256 + b);
            }
        }

        // ================= stage B: att = rel . QtT =================
        float catt[8][4];
        #pragma unroll
        for (int nt = 0; nt < 8; nt++)
            #pragma unroll
            for (int x = 0; x < 4; x++) catt[nt][x] = 0.f;

        #pragma unroll
        for (int kt = 0; kt < 8; kt++) {
            const uint32_t swz = (uint32_t)((((kt * 2 + cpar) * 16)) ^ lr4);
            #pragma unroll
            for (int np = 0; np < 4; np++) {
                uint32_t bh[4], bl[4];
                ldm4(bh, qtB  + np * 4096 + swz);
                ldm4(bl, qtBl + np * 4096 + swz);
                // interleave accumulators: RAW distance 2
                mma16816(catt[2 * np],     Ah[kt], bh[0], bh[1]);
                mma16816(catt[2 * np + 1], Ah[kt], bh[2], bh[3]);
                mma16816(catt[2 * np],     Al[kt], bh[0], bh[1]);
                mma16816(catt[2 * np + 1], Al[kt], bh[2], bh[3]);
                mma16816(catt[2 * np],     Ah[kt], bl[0], bl[1]);
                mma16816(catt[2 * np + 1], Ah[kt], bl[2], bl[3]);
            }
        }

        // ================= softmax in fragments =================
        uint32_t Wh[4][4], Wl[4][4];
        {
            float m0 = -1e30f, m1 = -1e30f;
            #pragma unroll
            for (int nt = 0; nt < 8; nt++) {
                m0 = fmaxf(m0, fmaxf(catt[nt][0], catt[nt][1]));
                m1 = fmaxf(m1, fmaxf(catt[nt][2], catt[nt][3]));
            }
            m0 = fmaxf(m0, __shfl_xor_sync(0xFFFFFFFFu, m0, 1));
            m0 = fmaxf(m0, __shfl_xor_sync(0xFFFFFFFFu, m0, 2));
            m1 = fmaxf(m1, __shfl_xor_sync(0xFFFFFFFFu, m1, 1));
            m1 = fmaxf(m1, __shfl_xor_sync(0xFFFFFFFFu, m1, 2));
            float s0 = 0.f, s1 = 0.f;
            #pragma unroll
            for (int nt = 0; nt < 8; nt++) {
                catt[nt][0] = __expf(catt[nt][0] - m0);
                catt[nt][1] = __expf(catt[nt][1] - m0);
                catt[nt][2] = __expf(catt[nt][2] - m1);
                catt[nt][3] = __expf(catt[nt][3] - m1);
                s0 += catt[nt][0] + catt[nt][1];
                s1 += catt[nt][2] + catt[nt][3];
            }
            s0 += __shfl_xor_sync(0xFFFFFFFFu, s0, 1);
            s0 += __shfl_xor_sync(0xFFFFFFFFu, s0, 2);
            s1 += __shfl_xor_sync(0xFFFFFFFFu, s1, 1);
            s1 += __shfl_xor_sync(0xFFFFFFFFu, s1, 2);
            const float i0 = 1.f / s0, i1 = 1.f / s1;
            #pragma unroll
            for (int j = 0; j < 4; j++) {
                split_pack(catt[2 * j][0] * i0, catt[2 * j][1] * i0, Wh[j][0], Wl[j][0]);
                split_pack(catt[2 * j][2] * i1, catt[2 * j][3] * i1, Wh[j][1], Wl[j][1]);
                split_pack(catt[2 * j + 1][0] * i0, catt[2 * j + 1][1] * i0, Wh[j][2], Wl[j][2]);
                split_pack(catt[2 * j + 1][2] * i1, catt[2 * j + 1][3] * i1, Wh[j][3], Wl[j][3]);
            }
        }

        // ================= fused stages C & D + epilogue =================
        float sc0 = 0.f, sc1 = 0.f;
        #pragma unroll
        for (int np = 0; np < 8; np++) {
            float cc0[4] = {0.f, 0.f, 0.f, 0.f};
            float cc1[4] = {0.f, 0.f, 0.f, 0.f};
            float cv0[4] = {0.f, 0.f, 0.f, 0.f};
            float cv1[4] = {0.f, 0.f, 0.f, 0.f};
            #pragma unroll
            for (int kt = 0; kt < 4; kt++) {
                const uint32_t swz = (uint32_t)((((kt * 2 + cpar) * 16)) ^ lr4);
                uint32_t bh[4], bl[4];
                ldm4(bh, mB  + np * 2048 + swz);
                ldm4(bl, mBl + np * 2048 + swz);
                mma16816(cc0, Wh[kt], bh[0], bh[1]);
                mma16816(cc1, Wh[kt], bh[2], bh[3]);
                mma16816(cc0, Wl[kt], bh[0], bh[1]);
                mma16816(cc1, Wl[kt], bh[2], bh[3]);
                mma16816(cc0, Wh[kt], bl[0], bl[1]);
                mma16816(cc1, Wh[kt], bl[2], bl[3]);
            }
            #pragma unroll
            for (int kt = 0; kt < 8; kt++) {
                const uint32_t swz = (uint32_t)((((kt * 2 + cpar) * 16)) ^ lr4);
                uint32_t bh[4], bl[4];
                ldm4(bh, w2B  + np * 4096 + swz);
                ldm4(bl, w2Bl + np * 4096 + swz);
                mma16816(cv0, Ah[kt], bh[0], bh[1]);
                mma16816(cv1, Ah[kt], bh[2], bh[3]);
                mma16816(cv0, Al[kt], bh[0], bh[1]);
                mma16816(cv1, Al[kt], bh[2], bh[3]);
                mma16816(cv0, Ah[kt], bl[0], bl[1]);
                mma16816(cv1, Ah[kt], bl[2], bl[3]);
            }
            {
                const int j0 = (2 * np) * 8 + 2 * q;
                const float h1a = s_h1[j0], h1b = s_h1[j0 + 1];
                sc0 += fmaxf(cc0[0] + h1a, 0.f) * cv0[0] + fmaxf(cc0[1] + h1b, 0.f) * cv0[1];
                sc1 += fmaxf(cc0[2] + h1a, 0.f) * cv0[2] + fmaxf(cc0[3] + h1b, 0.f) * cv0[3];
            }
            {
                const int j0 = (2 * np + 1) * 8 + 2 * q;
                const float h1a = s_h1[j0], h1b = s_h1[j0 + 1];
                sc0 += fmaxf(cc1[0] + h1a, 0.f) * cv1[0] + fmaxf(cc1[1] + h1b, 0.f) * cv1[1];
                sc1 += fmaxf(cc1[2] + h1a, 0.f) * cv1[2] + fmaxf(cc1[3] + h1b, 0.f) * cv1[3];
            }
        }

        sc0 += __shfl_xor_sync(0xFFFFFFFFu, sc0, 1);
        sc0 += __shfl_xor_sync(0xFFFFFFFFu, sc0, 2);
        sc1 += __shfl_xor_sync(0xFFFFFFFFu, sc1, 1);
        sc1 += __shfl_xor_sync(0xFFFFFFFFu, sc1, 2);
        if (q == 0) {
            const int r0 = 16 * wid + nidx;
            const int r1 = r0 + 8;
            const int a0 = tile * TILE_A + r0;
            const int a1 = tile * TILE_A + r1;
            if (a0 < A_SIZE) {
                float s = sc0 + s_db2[2 * r0] + s_db2[2 * r0 + 1];
                g_scores[a0] = s;
                float nm = fmaxf(lm, s);
                lz = lz * __expf(lm - nm) + __expf(s - nm);
                lm = nm;
            }
            if (a1 < A_SIZE) {
                float s = sc1 + s_db2[2 * r1] + s_db2[2 * r1 + 1];
                g_scores[a1] = s;
                float nm = fmaxf(lm, s);
                lz = lz * __expf(lm - nm) + __expf(s - nm);
                lm = nm;
            }
        }
        __syncthreads();
    }

    // ================= fused global softmax reduction =================
    #pragma unroll
    for (int o = 16; o > 0; o >>= 1) {
        float om = __shfl_xor_sync(0xFFFFFFFFu, lm, o);
        float oz = __shfl_xor_sync(0xFFFFFFFFu, lz, o);
        oz_merge(lm, lz, om, oz);
    }
    if (lane == 0) { s_rm[wid] = lm; s_rz[wid] = lz; }
    __syncthreads();
    if (tid == 0) {
        float M = s_rm[0], Z = s_rz[0];
        #pragma unroll
        for (int w = 1; w < NWARPS; w++) oz_merge(M, Z, s_rm[w], s_rz[w]);
        g_pmax[blockIdx.x] = M;
        g_psum[blockIdx.x] = Z;
        __threadfence();
        int old = atomicAdd(&g_done, 1);
        s_fl[0] = (old == (int)gridDim.x - 1) ? 1 : 0;
    }
    __syncthreads();
    if (s_fl[0]) {
        if (wid == 0) {
            float M = -1e30f, Z = 0.f;
            for (int i = lane; i < (int)gridDim.x; i += 32)
                oz_merge(M, Z, g_pmax[i], g_psum[i]);
            #pragma unroll
            for (int o = 16; o > 0; o >>= 1) {
                float om = __shfl_xor_sync(0xFFFFFFFFu, M, o);
                float oz = __shfl_xor_sync(0xFFFFFFFFu, Z, o);
                oz_merge(M, Z, om, oz);
            }
            if (lane == 0) {
                g_stats[0] = M; g_stats[1] = Z;
                __threadfence();
                atomicExch(&g_flag, 1);
            }
        }
    } else if (tid == 0) {
        while (atomicAdd(&g_flag, 0) == 0) { __nanosleep(64); }
    }
    __syncthreads();

    // ================= fused normalize =================
    {
        const float gm  = g_stats[0];
        const float inv = 1.f / g_stats[1];
        for (int i = blockIdx.x * NTHREADS + tid; i < A_SIZE; i += gridDim.x * NTHREADS)
            out[i] = __expf(g_scores[i] - gm) * inv;
    }
}

// ---------------- launch ----------------
extern "C" void kernel_launch(void* const* d_in, const int* in_sizes, int n_in,
                              void* d_out, int out_size) {
    const int*   action_ids = (const int*)d_in[0];
    const float* emb        = (const float*)d_in[1];
    const float* question_t = (const float*)d_in[2];
    const float* history_t  = (const float*)d_in[3];
    const float* W1         = (const float*)d_in[4];
    const float* b1         = (const float*)d_in[5];
    const float* W2         = (const float*)d_in[6];
    const float* b2         = (const float*)d_in[7];
    float* out = (float*)d_out;

    prep_all<<<161, 256>>>(W1, b1, question_t, history_t, W2);

    cudaFuncSetAttribute(score_kernel,
                         cudaFuncAttributeMaxDynamicSharedMemorySize, SM_TOTAL);
    score_kernel<<<NBLOCKS, NTHREADS, SM_TOTAL>>>(action_ids, emb, b2, out);
}